// round 2
// baseline (speedup 1.0000x reference)
#include <cuda_runtime.h>
#include <cstddef>

// Problem constants
#define Hh      8
#define SS      2048
#define DM      512
#define DH      64
#define BATCH   4
#define BHN     (BATCH * Hh)          // 32
#define MQ      (BATCH * SS)          // 8192
#define OUT_ELEMS ((size_t)BATCH * SS * DM)  // 4194304

// Scratch (allocation-free: __device__ globals). 4 x 16.8 MB = 67 MB.
__device__ float g_Q [BHN * SS * DH];
__device__ float g_K [BHN * SS * DH];
__device__ float g_V [BHN * SS * DH];
__device__ float g_Hd[BHN * SS * DH];

// ---------------------------------------------------------------------------
// Kernel 1: input projection  C = X @ W^T + b, scattered to [B,H,S,64] layout.
// X: [8192, 512], W: [512, 512] (row n = output feature, K-major), b: [512]
// which: 0 -> g_Q, 1 -> g_K, 2 -> g_V
// grid (DM/128=4, MQ/128=64), block 256
// ---------------------------------------------------------------------------
__global__ __launch_bounds__(256, 2)
void proj_kernel(const float* __restrict__ X, const float* __restrict__ W,
                 const float* __restrict__ bias, int which)
{
    __shared__ float As[8][128];
    __shared__ float Bs[8][128];

    float* outp = (which == 0) ? g_Q : (which == 1) ? g_K : g_V;

    const int t   = threadIdx.x;
    const int m0  = blockIdx.y * 128;
    const int n0  = blockIdx.x * 128;
    const int row = t >> 1;      // 0..127
    const int seg = t & 1;       // 0..1 (which half of BK=8)
    const int tx  = t & 15;
    const int ty  = t >> 4;

    float acc[8][8];
#pragma unroll
    for (int i = 0; i < 8; i++)
#pragma unroll
        for (int j = 0; j < 8; j++) acc[i][j] = 0.f;

    for (int k0 = 0; k0 < DM; k0 += 8) {
        float4 av = *(const float4*)(X + (size_t)(m0 + row) * DM + k0 + seg * 4);
        float4 bv = *(const float4*)(W + (size_t)(n0 + row) * DM + k0 + seg * 4);
        As[seg*4+0][row] = av.x; As[seg*4+1][row] = av.y;
        As[seg*4+2][row] = av.z; As[seg*4+3][row] = av.w;
        Bs[seg*4+0][row] = bv.x; Bs[seg*4+1][row] = bv.y;
        Bs[seg*4+2][row] = bv.z; Bs[seg*4+3][row] = bv.w;
        __syncthreads();
#pragma unroll
        for (int kk = 0; kk < 8; kk++) {
            float a[8], b[8];
#pragma unroll
            for (int i = 0; i < 8; i++) a[i] = As[kk][ty*8 + i];
#pragma unroll
            for (int j = 0; j < 8; j++) b[j] = Bs[kk][tx*8 + j];
#pragma unroll
            for (int i = 0; i < 8; i++)
#pragma unroll
                for (int j = 0; j < 8; j++) acc[i][j] += a[i] * b[j];
        }
        __syncthreads();
    }

#pragma unroll
    for (int i = 0; i < 8; i++) {
        const int m  = m0 + ty*8 + i;
        const int b_ = m / SS;
        const int s_ = m % SS;
#pragma unroll
        for (int j = 0; j < 8; j++) {
            const int n = n0 + tx*8 + j;
            const int h = n >> 6, d = n & 63;
            outp[(((size_t)(b_*Hh + h) * SS) + s_) * DH + d] = acc[i][j] + bias[n];
        }
    }
}

// ---------------------------------------------------------------------------
// Kernel 2: scores per (b,h): raw = (Q @ K^T) * 0.125 + mask -> att region
// grid (16, 16, 32), block 256
// ---------------------------------------------------------------------------
__global__ __launch_bounds__(256, 2)
void scores_kernel(const float* __restrict__ mask, float* __restrict__ att)
{
    __shared__ float As[8][128];
    __shared__ float Bs[8][128];

    const int bh = blockIdx.z;
    const float* Q = g_Q + (size_t)bh * SS * DH;
    const float* K = g_K + (size_t)bh * SS * DH;

    const int t   = threadIdx.x;
    const int m0  = blockIdx.y * 128;   // query tile
    const int n0  = blockIdx.x * 128;   // key tile
    const int row = t >> 1;
    const int seg = t & 1;
    const int tx  = t & 15;
    const int ty  = t >> 4;

    float acc[8][8];
#pragma unroll
    for (int i = 0; i < 8; i++)
#pragma unroll
        for (int j = 0; j < 8; j++) acc[i][j] = 0.f;

    for (int k0 = 0; k0 < DH; k0 += 8) {
        float4 av = *(const float4*)(Q + (size_t)(m0 + row) * DH + k0 + seg * 4);
        float4 bv = *(const float4*)(K + (size_t)(n0 + row) * DH + k0 + seg * 4);
        As[seg*4+0][row] = av.x; As[seg*4+1][row] = av.y;
        As[seg*4+2][row] = av.z; As[seg*4+3][row] = av.w;
        Bs[seg*4+0][row] = bv.x; Bs[seg*4+1][row] = bv.y;
        Bs[seg*4+2][row] = bv.z; Bs[seg*4+3][row] = bv.w;
        __syncthreads();
#pragma unroll
        for (int kk = 0; kk < 8; kk++) {
            float a[8], b[8];
#pragma unroll
            for (int i = 0; i < 8; i++) a[i] = As[kk][ty*8 + i];
#pragma unroll
            for (int j = 0; j < 8; j++) b[j] = Bs[kk][tx*8 + j];
#pragma unroll
            for (int i = 0; i < 8; i++)
#pragma unroll
                for (int j = 0; j < 8; j++) acc[i][j] += a[i] * b[j];
        }
        __syncthreads();
    }

#pragma unroll
    for (int i = 0; i < 8; i++) {
        const int q = m0 + ty*8 + i;
#pragma unroll
        for (int j = 0; j < 8; j++) {
            const int k = n0 + tx*8 + j;
            att[((size_t)bh * SS + q) * SS + k] =
                acc[i][j] * 0.125f + mask[(size_t)q * SS + k];
        }
    }
}

// ---------------------------------------------------------------------------
// Kernel 3: in-place row softmax over att (row length 2048).
// grid 32768, block 256, 8 elements/thread
// ---------------------------------------------------------------------------
__global__ __launch_bounds__(256)
void softmax_kernel(float* __restrict__ att)
{
    __shared__ float red[8];
    const size_t row = blockIdx.x;
    float* p = att + row * SS;
    const int t = threadIdx.x;

    float4 v0 = ((const float4*)p)[t*2 + 0];
    float4 v1 = ((const float4*)p)[t*2 + 1];

    float mx = fmaxf(fmaxf(fmaxf(v0.x, v0.y), fmaxf(v0.z, v0.w)),
                     fmaxf(fmaxf(v1.x, v1.y), fmaxf(v1.z, v1.w)));
#pragma unroll
    for (int off = 16; off > 0; off >>= 1)
        mx = fmaxf(mx, __shfl_xor_sync(0xFFFFFFFFu, mx, off));
    if ((t & 31) == 0) red[t >> 5] = mx;
    __syncthreads();
    float bmx = red[0];
#pragma unroll
    for (int w = 1; w < 8; w++) bmx = fmaxf(bmx, red[w]);

    v0.x = expf(v0.x - bmx); v0.y = expf(v0.y - bmx);
    v0.z = expf(v0.z - bmx); v0.w = expf(v0.w - bmx);
    v1.x = expf(v1.x - bmx); v1.y = expf(v1.y - bmx);
    v1.z = expf(v1.z - bmx); v1.w = expf(v1.w - bmx);

    float sm = (v0.x + v0.y + v0.z + v0.w) + (v1.x + v1.y + v1.z + v1.w);
#pragma unroll
    for (int off = 16; off > 0; off >>= 1)
        sm += __shfl_xor_sync(0xFFFFFFFFu, sm, off);
    __syncthreads();               // red[] reuse
    if ((t & 31) == 0) red[t >> 5] = sm;
    __syncthreads();
    float bsm = 0.f;
#pragma unroll
    for (int w = 0; w < 8; w++) bsm += red[w];
    const float inv = 1.0f / bsm;

    v0.x *= inv; v0.y *= inv; v0.z *= inv; v0.w *= inv;
    v1.x *= inv; v1.y *= inv; v1.z *= inv; v1.w *= inv;
    ((float4*)p)[t*2 + 0] = v0;
    ((float4*)p)[t*2 + 1] = v1;
}

// ---------------------------------------------------------------------------
// Kernel 4: PV GEMM per (b,h): Hd = att @ V.   M=2048, N=64, K=2048.
// grid (16, 32): x = m-tile, y = bh. block 256, tile 128x64, BK=16, 8x4/thread
// ---------------------------------------------------------------------------
__global__ __launch_bounds__(256, 2)
void av_kernel(const float* __restrict__ att)
{
    __shared__ float As[16][128];
    __shared__ float Bs[16][64];

    const int bh = blockIdx.y;
    const float* A = att + (size_t)bh * SS * SS;
    const float* V = g_V + (size_t)bh * SS * DH;

    const int t  = threadIdx.x;
    const int m0 = blockIdx.x * 128;
    const int tx = t & 15;
    const int ty = t >> 4;

    float acc[8][4];
#pragma unroll
    for (int i = 0; i < 8; i++)
#pragma unroll
        for (int j = 0; j < 4; j++) acc[i][j] = 0.f;

    for (int k0 = 0; k0 < SS; k0 += 16) {
#pragma unroll
        for (int r = 0; r < 2; r++) {
            const int idx  = t + r * 256;
            const int arow = idx >> 2;   // 0..127
            const int aseg = idx & 3;    // 0..3
            float4 av = *(const float4*)(A + (size_t)(m0 + arow) * SS + k0 + aseg * 4);
            As[aseg*4+0][arow] = av.x; As[aseg*4+1][arow] = av.y;
            As[aseg*4+2][arow] = av.z; As[aseg*4+3][arow] = av.w;
        }
        {
            const int bkk  = t >> 4;     // 0..15
            const int bseg = t & 15;     // 0..15
            float4 bv = *(const float4*)(V + (size_t)(k0 + bkk) * DH + bseg * 4);
            *(float4*)(&Bs[bkk][bseg * 4]) = bv;
        }
        __syncthreads();
#pragma unroll
        for (int kk = 0; kk < 16; kk++) {
            float a[8], b[4];
#pragma unroll
            for (int i = 0; i < 8; i++) a[i] = As[kk][ty*8 + i];
#pragma unroll
            for (int j = 0; j < 4; j++) b[j] = Bs[kk][tx*4 + j];
#pragma unroll
            for (int i = 0; i < 8; i++)
#pragma unroll
                for (int j = 0; j < 4; j++) acc[i][j] += a[i] * b[j];
        }
        __syncthreads();
    }

#pragma unroll
    for (int i = 0; i < 8; i++)
#pragma unroll
        for (int j = 0; j < 4; j++)
            g_Hd[((size_t)bh * SS + m0 + ty*8 + i) * DH + tx*4 + j] = acc[i][j];
}

// ---------------------------------------------------------------------------
// Kernel 5: output projection  out = Hd(reinterleaved) @ Wo^T + bo
// grid (4, 64), block 256
// ---------------------------------------------------------------------------
__global__ __launch_bounds__(256, 2)
void oproj_kernel(const float* __restrict__ Wo, const float* __restrict__ bo,
                  float* __restrict__ out)
{
    __shared__ float As[8][128];
    __shared__ float Bs[8][128];

    const int t   = threadIdx.x;
    const int m0  = blockIdx.y * 128;
    const int n0  = blockIdx.x * 128;
    const int row = t >> 1;
    const int seg = t & 1;
    const int tx  = t & 15;
    const int ty  = t >> 4;

    float acc[8][8];
#pragma unroll
    for (int i = 0; i < 8; i++)
#pragma unroll
        for (int j = 0; j < 8; j++) acc[i][j] = 0.f;

    const int m  = m0 + row;
    const int b_ = m / SS;
    const int s_ = m % SS;

    for (int k0 = 0; k0 < DM; k0 += 8) {
        const int j0 = k0 + seg * 4;       // stays within one 64-wide head block
        const int h  = j0 >> 6, d = j0 & 63;
        float4 av = *(const float4*)(g_Hd + (((size_t)(b_*Hh + h) * SS) + s_) * DH + d);
        float4 bv = *(const float4*)(Wo + (size_t)(n0 + row) * DM + j0);
        As[seg*4+0][row] = av.x; As[seg*4+1][row] = av.y;
        As[seg*4+2][row] = av.z; As[seg*4+3][row] = av.w;
        Bs[seg*4+0][row] = bv.x; Bs[seg*4+1][row] = bv.y;
        Bs[seg*4+2][row] = bv.z; Bs[seg*4+3][row] = bv.w;
        __syncthreads();
#pragma unroll
        for (int kk = 0; kk < 8; kk++) {
            float a[8], b[8];
#pragma unroll
            for (int i = 0; i < 8; i++) a[i] = As[kk][ty*8 + i];
#pragma unroll
            for (int j = 0; j < 8; j++) b[j] = Bs[kk][tx*8 + j];
#pragma unroll
            for (int i = 0; i < 8; i++)
#pragma unroll
                for (int j = 0; j < 8; j++) acc[i][j] += a[i] * b[j];
        }
        __syncthreads();
    }

#pragma unroll
    for (int i = 0; i < 8; i++) {
        const int mm = m0 + ty*8 + i;
#pragma unroll
        for (int j = 0; j < 8; j++) {
            const int n = n0 + tx*8 + j;
            out[(size_t)mm * DM + n] = acc[i][j] + bo[n];
        }
    }
}

// ---------------------------------------------------------------------------
extern "C" void kernel_launch(void* const* d_in, const int* in_sizes, int n_in,
                              void* d_out, int out_size)
{
    const float* queries = (const float*)d_in[0];
    const float* keys    = (const float*)d_in[1];
    const float* values  = (const float*)d_in[2];
    const float* mask    = (const float*)d_in[3];
    const float* Wq      = (const float*)d_in[4];
    const float* bq      = (const float*)d_in[5];
    const float* Wk      = (const float*)d_in[6];
    const float* bk      = (const float*)d_in[7];
    const float* Wv      = (const float*)d_in[8];
    const float* bv      = (const float*)d_in[9];
    const float* Wo      = (const float*)d_in[10];
    const float* bo      = (const float*)d_in[11];

    float* out = (float*)d_out;            // [4, 2048, 512]
    float* att = out + OUT_ELEMS;          // [4, 8, 2048, 2048]

    dim3 projGrid(DM / 128, MQ / 128);     // (4, 64)
    proj_kernel<<<projGrid, 256>>>(queries, Wq, bq, 0);
    proj_kernel<<<projGrid, 256>>>(keys,    Wk, bk, 1);
    proj_kernel<<<projGrid, 256>>>(values,  Wv, bv, 2);

    dim3 scoreGrid(SS / 128, SS / 128, BHN);  // (16, 16, 32)
    scores_kernel<<<scoreGrid, 256>>>(mask, att);

    softmax_kernel<<<BHN * SS, 256>>>(att);

    dim3 avGrid(SS / 128, BHN);            // (16, 32)
    av_kernel<<<avGrid, 256>>>(att);

    dim3 oGrid(DM / 128, MQ / 128);        // (4, 64)
    oproj_kernel<<<oGrid, 256>>>(Wo, bo, out);
}

// round 6
// speedup vs baseline: 1.4767x; 1.4767x over previous
#include <cuda_runtime.h>
#include <cuda_bf16.h>
#include <cstdint>
#include <cstddef>

// Problem constants
#define Hh      8
#define SS      2048
#define DM      512
#define DH      64
#define BATCH   4
#define BHN     (BATCH * Hh)          // 32
#define MQ      (BATCH * SS)          // 8192
#define OUT_ELEMS ((size_t)BATCH * SS * DM)  // 4194304

// Scratch (allocation-free: __device__ globals).
__device__ __nv_bfloat16 g_Qh [BHN * SS * DH];
__device__ __nv_bfloat16 g_Ql [BHN * SS * DH];
__device__ __nv_bfloat16 g_Kh [BHN * SS * DH];
__device__ __nv_bfloat16 g_Kl [BHN * SS * DH];
__device__ __nv_bfloat16 g_Vth[BHN * DH * SS];   // V^T hi: [bh][d][s]
__device__ __nv_bfloat16 g_Vtl[BHN * DH * SS];   // V^T lo
__device__ float g_Hd[BHN * SS * DH];

// ===========================================================================
// Warp-level MMA helpers (sm_80-compatible PTX: works at compute_103 target)
// ===========================================================================
__device__ __forceinline__ uint32_t smem_u32(const void* p) {
    uint32_t a;
    asm("{ .reg .u64 t; cvta.to.shared.u64 t, %1; cvt.u32.u64 %0, t; }"
        : "=r"(a) : "l"(p));
    return a;
}

__device__ __forceinline__ void mma16816(float* c, const uint32_t* a, const uint32_t* b) {
    asm volatile(
        "mma.sync.aligned.m16n8k16.row.col.f32.bf16.bf16.f32 "
        "{%0,%1,%2,%3}, {%4,%5,%6,%7}, {%8,%9}, {%0,%1,%2,%3};"
        : "+f"(c[0]), "+f"(c[1]), "+f"(c[2]), "+f"(c[3])
        : "r"(a[0]), "r"(a[1]), "r"(a[2]), "r"(a[3]), "r"(b[0]), "r"(b[1]));
}
__device__ __forceinline__ void ldm_x4(uint32_t* r, uint32_t addr) {
    asm volatile("ldmatrix.sync.aligned.m8n8.x4.shared.b16 {%0,%1,%2,%3}, [%4];"
        : "=r"(r[0]), "=r"(r[1]), "=r"(r[2]), "=r"(r[3]) : "r"(addr));
}
__device__ __forceinline__ void ldm_x2(uint32_t* r, uint32_t addr) {
    asm volatile("ldmatrix.sync.aligned.m8n8.x2.shared.b16 {%0,%1}, [%2];"
        : "=r"(r[0]), "=r"(r[1]) : "r"(addr));
}

#define SPAD 72   // row pitch in bf16 elems (144B) -> conflict-free ldmatrix

// ---------------------------------------------------------------------------
// Kernel 1: input projection  C = X @ W^T + b.
// which: 0 -> Q (bf16 hi/lo, [bh][s][d]), 1 -> K (same), 2 -> V^T (bf16 hi/lo, [bh][d][s])
// grid (4, 64), block 256
// ---------------------------------------------------------------------------
__global__ __launch_bounds__(256, 2)
void proj_kernel(const float* __restrict__ X, const float* __restrict__ W,
                 const float* __restrict__ bias, int which)
{
    __shared__ float As[8][128];
    __shared__ float Bs[8][128];

    const int t   = threadIdx.x;
    const int m0  = blockIdx.y * 128;
    const int n0  = blockIdx.x * 128;
    const int row = t >> 1;
    const int seg = t & 1;
    const int tx  = t & 15;
    const int ty  = t >> 4;

    float acc[8][8];
#pragma unroll
    for (int i = 0; i < 8; i++)
#pragma unroll
        for (int j = 0; j < 8; j++) acc[i][j] = 0.f;

    for (int k0 = 0; k0 < DM; k0 += 8) {
        float4 av = *(const float4*)(X + (size_t)(m0 + row) * DM + k0 + seg * 4);
        float4 bv = *(const float4*)(W + (size_t)(n0 + row) * DM + k0 + seg * 4);
        As[seg*4+0][row] = av.x; As[seg*4+1][row] = av.y;
        As[seg*4+2][row] = av.z; As[seg*4+3][row] = av.w;
        Bs[seg*4+0][row] = bv.x; Bs[seg*4+1][row] = bv.y;
        Bs[seg*4+2][row] = bv.z; Bs[seg*4+3][row] = bv.w;
        __syncthreads();
#pragma unroll
        for (int kk = 0; kk < 8; kk++) {
            float a[8], b[8];
#pragma unroll
            for (int i = 0; i < 8; i++) a[i] = As[kk][ty*8 + i];
#pragma unroll
            for (int j = 0; j < 8; j++) b[j] = Bs[kk][tx*8 + j];
#pragma unroll
            for (int i = 0; i < 8; i++)
#pragma unroll
                for (int j = 0; j < 8; j++) acc[i][j] += a[i] * b[j];
        }
        __syncthreads();
    }

#pragma unroll
    for (int i = 0; i < 8; i++) {
        const int m  = m0 + ty*8 + i;
        const int b_ = m / SS;
        const int s_ = m % SS;
#pragma unroll
        for (int j = 0; j < 8; j++) {
            const int n = n0 + tx*8 + j;
            const int h = n >> 6, d = n & 63;
            const int bh = b_ * Hh + h;
            const float v = acc[i][j] + bias[n];
            __nv_bfloat16 hi = __float2bfloat16(v);
            __nv_bfloat16 lo = __float2bfloat16(v - __bfloat162float(hi));
            if (which == 2) {
                const size_t it = ((size_t)bh * DH + d) * SS + s_;
                g_Vth[it] = hi; g_Vtl[it] = lo;
            } else {
                const size_t idx = ((size_t)bh * SS + s_) * DH + d;
                if (which == 0) { g_Qh[idx] = hi; g_Ql[idx] = lo; }
                else            { g_Kh[idx] = hi; g_Kl[idx] = lo; }
            }
        }
    }
}

// ---------------------------------------------------------------------------
// Kernel 2: scores via mma.sync bf16, compensated hi/lo.
// S = (Qh*Kh + Qh*Kl + Ql*Kh) * 0.125 + mask -> att
// grid (16, 16, 32), block 256 (8 warps: 2 x 4 -> each warp m64 x n32)
// dynamic smem: 4 tiles of [128][72] bf16 = 73728 B
// ---------------------------------------------------------------------------
#define SC_QH 0
#define SC_QL (128 * SPAD)
#define SC_KH (2 * 128 * SPAD)
#define SC_KL (3 * 128 * SPAD)
#define SCORES_SMEM (4 * 128 * SPAD * 2)

__global__ __launch_bounds__(256)
void scores_mma_kernel(const float* __restrict__ mask, float* __restrict__ att)
{
    extern __shared__ __nv_bfloat16 sm[];
    const int t    = threadIdx.x;
    const int wid  = t >> 5;
    const int lane = t & 31;

    const int bh = blockIdx.z;
    const int m0 = blockIdx.y * 128;
    const int n0 = blockIdx.x * 128;

    // Load 4 operand tiles (128 rows x 64 bf16 each) into padded smem.
    {
        const size_t rb = (size_t)bh * SS * DH;
        const int row  = t >> 1;
        const int half = t & 1;
        const uint4* sQh = (const uint4*)(g_Qh + rb + (size_t)(m0 + row) * DH) + half * 4;
        const uint4* sQl = (const uint4*)(g_Ql + rb + (size_t)(m0 + row) * DH) + half * 4;
        const uint4* sKh = (const uint4*)(g_Kh + rb + (size_t)(n0 + row) * DH) + half * 4;
        const uint4* sKl = (const uint4*)(g_Kl + rb + (size_t)(n0 + row) * DH) + half * 4;
        uint4* dQh = (uint4*)(sm + SC_QH + row * SPAD + half * 32);
        uint4* dQl = (uint4*)(sm + SC_QL + row * SPAD + half * 32);
        uint4* dKh = (uint4*)(sm + SC_KH + row * SPAD + half * 32);
        uint4* dKl = (uint4*)(sm + SC_KL + row * SPAD + half * 32);
#pragma unroll
        for (int i = 0; i < 4; i++) {
            dQh[i] = sQh[i]; dQl[i] = sQl[i];
            dKh[i] = sKh[i]; dKl[i] = sKl[i];
        }
    }
    __syncthreads();

    const uint32_t sbase = smem_u32(sm);
    const int warp_m = wid >> 2;          // 0..1 -> 64-row slab
    const int warp_n = wid & 3;           // 0..3 -> 32-col slab

    float acc[4][4][4];
#pragma unroll
    for (int mt = 0; mt < 4; mt++)
#pragma unroll
        for (int nt = 0; nt < 4; nt++)
#pragma unroll
            for (int e = 0; e < 4; e++) acc[mt][nt][e] = 0.f;

    const int l16   = lane & 15;
    const int arow  = warp_m * 64 + (lane & 15);
    const int acol8 = (lane >> 4) * 8;
    const int brow  = warp_n * 32 + (l16 & 7);
    const int bcol8 = (l16 >> 3) * 8;

#pragma unroll
    for (int c = 0; c < 3; c++) {
        const int Aoff = (c < 2) ? SC_QH : SC_QL;
        const int Boff = (c == 1) ? SC_KL : SC_KH;
#pragma unroll
        for (int ks = 0; ks < 4; ks++) {
            const int k0 = ks * 16;
            uint32_t a[4][4], b[4][2];
#pragma unroll
            for (int mt = 0; mt < 4; mt++)
                ldm_x4(a[mt], sbase + 2u * (Aoff + (arow + mt*16) * SPAD + k0 + acol8));
#pragma unroll
            for (int nt = 0; nt < 4; nt++)
                ldm_x2(b[nt], sbase + 2u * (Boff + (brow + nt*8) * SPAD + k0 + bcol8));
#pragma unroll
            for (int mt = 0; mt < 4; mt++)
#pragma unroll
                for (int nt = 0; nt < 4; nt++)
                    mma16816(acc[mt][nt], a[mt], b[nt]);
        }
    }

    // Epilogue: scale + mask -> att
    const int qrow = m0 + warp_m * 64 + (lane >> 2);
    const int cb0  = n0 + warp_n * 32 + (lane & 3) * 2;
#pragma unroll
    for (int mt = 0; mt < 4; mt++) {
        const int r0 = qrow + mt * 16;
        const int r1 = r0 + 8;
        const float* mr0 = mask + (size_t)r0 * SS;
        const float* mr1 = mask + (size_t)r1 * SS;
        float* ar0 = att + ((size_t)bh * SS + r0) * SS;
        float* ar1 = att + ((size_t)bh * SS + r1) * SS;
#pragma unroll
        for (int nt = 0; nt < 4; nt++) {
            const int cb = cb0 + nt * 8;
            float2 mv0 = *(const float2*)(mr0 + cb);
            float2 mv1 = *(const float2*)(mr1 + cb);
            float2 o0, o1;
            o0.x = acc[mt][nt][0] * 0.125f + mv0.x;
            o0.y = acc[mt][nt][1] * 0.125f + mv0.y;
            o1.x = acc[mt][nt][2] * 0.125f + mv1.x;
            o1.y = acc[mt][nt][3] * 0.125f + mv1.y;
            *(float2*)(ar0 + cb) = o0;
            *(float2*)(ar1 + cb) = o1;
        }
    }
}

// ---------------------------------------------------------------------------
// Kernel 3: in-place row softmax over att (row length 2048).
// ---------------------------------------------------------------------------
__global__ __launch_bounds__(256)
void softmax_kernel(float* __restrict__ att)
{
    __shared__ float red[8];
    const size_t row = blockIdx.x;
    float* p = att + row * SS;
    const int t = threadIdx.x;

    float4 v0 = ((const float4*)p)[t*2 + 0];
    float4 v1 = ((const float4*)p)[t*2 + 1];

    float mx = fmaxf(fmaxf(fmaxf(v0.x, v0.y), fmaxf(v0.z, v0.w)),
                     fmaxf(fmaxf(v1.x, v1.y), fmaxf(v1.z, v1.w)));
#pragma unroll
    for (int off = 16; off > 0; off >>= 1)
        mx = fmaxf(mx, __shfl_xor_sync(0xFFFFFFFFu, mx, off));
    if ((t & 31) == 0) red[t >> 5] = mx;
    __syncthreads();
    float bmx = red[0];
#pragma unroll
    for (int w = 1; w < 8; w++) bmx = fmaxf(bmx, red[w]);

    v0.x = expf(v0.x - bmx); v0.y = expf(v0.y - bmx);
    v0.z = expf(v0.z - bmx); v0.w = expf(v0.w - bmx);
    v1.x = expf(v1.x - bmx); v1.y = expf(v1.y - bmx);
    v1.z = expf(v1.z - bmx); v1.w = expf(v1.w - bmx);

    float sm = (v0.x + v0.y + v0.z + v0.w) + (v1.x + v1.y + v1.z + v1.w);
#pragma unroll
    for (int off = 16; off > 0; off >>= 1)
        sm += __shfl_xor_sync(0xFFFFFFFFu, sm, off);
    __syncthreads();
    if ((t & 31) == 0) red[t >> 5] = sm;
    __syncthreads();
    float bsm = 0.f;
#pragma unroll
    for (int w = 0; w < 8; w++) bsm += red[w];
    const float inv = 1.0f / bsm;

    v0.x *= inv; v0.y *= inv; v0.z *= inv; v0.w *= inv;
    v1.x *= inv; v1.y *= inv; v1.z *= inv; v1.w *= inv;
    ((float4*)p)[t*2 + 0] = v0;
    ((float4*)p)[t*2 + 1] = v1;
}

// ---------------------------------------------------------------------------
// Kernel 4: PV via mma.sync bf16, compensated. Hd = att @ V per (b,h).
// att fp32 -> hi/lo on the fly; V^T bf16 hi/lo preloaded by proj.
// grid (16, 32): x = m-tile(128), y = bh. block 256 (8 warps: 2 x 4 -> m64 x n16)
// smem: attH/attL [128][72], Vh/Vl [64][72]  = 55296 B
// ---------------------------------------------------------------------------
#define AV_AH 0
#define AV_AL (128 * SPAD)
#define AV_VH (2 * 128 * SPAD)
#define AV_VL (2 * 128 * SPAD + 64 * SPAD)
#define AV_SMEM ((2 * 128 * SPAD + 2 * 64 * SPAD) * 2)

__global__ __launch_bounds__(256)
void av_mma_kernel(const float* __restrict__ att)
{
    extern __shared__ __nv_bfloat16 sm[];
    const int t    = threadIdx.x;
    const int wid  = t >> 5;
    const int lane = t & 31;

    const int bh = blockIdx.y;
    const int m0 = blockIdx.x * 128;

    const uint32_t sbase = smem_u32(sm);
    const int warp_m = wid >> 2;          // 0..1
    const int warp_n = wid & 3;           // 0..3 -> 16 cols

    float acc[4][2][4];
#pragma unroll
    for (int mt = 0; mt < 4; mt++)
#pragma unroll
        for (int nt = 0; nt < 2; nt++)
#pragma unroll
            for (int e = 0; e < 4; e++) acc[mt][nt][e] = 0.f;

    const int l16   = lane & 15;
    const int arow  = warp_m * 64 + (lane & 15);
    const int acol8 = (lane >> 4) * 8;
    const int brow  = warp_n * 16 + (l16 & 7);
    const int bcol8 = (l16 >> 3) * 8;

    // load indices
    const int lrow  = t >> 1;             // 0..127 (att rows)
    const int lhalf = t & 1;
    const int vrow  = t >> 2;             // 0..63  (V^T rows)
    const int vq    = t & 3;

    const float* attrow = att + ((size_t)bh * SS + m0 + lrow) * SS;
    const __nv_bfloat16* vth = g_Vth + ((size_t)bh * DH + vrow) * SS;
    const __nv_bfloat16* vtl = g_Vtl + ((size_t)bh * DH + vrow) * SS;

    for (int kb = 0; kb < SS; kb += 64) {
        // att fp32 -> hi/lo bf16 smem
        {
            const float4* src = (const float4*)(attrow + kb + lhalf * 32);
            __nv_bfloat16* dh = sm + AV_AH + lrow * SPAD + lhalf * 32;
            __nv_bfloat16* dl = sm + AV_AL + lrow * SPAD + lhalf * 32;
#pragma unroll
            for (int i = 0; i < 8; i++) {
                float4 v = src[i];
                __nv_bfloat16 h0 = __float2bfloat16(v.x);
                __nv_bfloat16 h1 = __float2bfloat16(v.y);
                __nv_bfloat16 h2 = __float2bfloat16(v.z);
                __nv_bfloat16 h3 = __float2bfloat16(v.w);
                __nv_bfloat16 l0 = __float2bfloat16(v.x - __bfloat162float(h0));
                __nv_bfloat16 l1 = __float2bfloat16(v.y - __bfloat162float(h1));
                __nv_bfloat16 l2 = __float2bfloat16(v.z - __bfloat162float(h2));
                __nv_bfloat16 l3 = __float2bfloat16(v.w - __bfloat162float(h3));
                __nv_bfloat162* ph = (__nv_bfloat162*)(dh + i * 4);
                __nv_bfloat162* pl = (__nv_bfloat162*)(dl + i * 4);
                ph[0] = __nv_bfloat162(h0, h1); ph[1] = __nv_bfloat162(h2, h3);
                pl[0] = __nv_bfloat162(l0, l1); pl[1] = __nv_bfloat162(l2, l3);
            }
        }
        // V^T tiles
        {
#pragma unroll
            for (int i = 0; i < 2; i++) {
                const int col = vq * 16 + i * 8;
                *(uint4*)(sm + AV_VH + vrow * SPAD + col) = *(const uint4*)(vth + kb + col);
                *(uint4*)(sm + AV_VL + vrow * SPAD + col) = *(const uint4*)(vtl + kb + col);
            }
        }
        __syncthreads();

#pragma unroll
        for (int ks = 0; ks < 4; ks++) {
            const int k0 = ks * 16;
            uint32_t aH[4][4], aL[4][4], bH[2][2], bL[2][2];
#pragma unroll
            for (int mt = 0; mt < 4; mt++) {
                ldm_x4(aH[mt], sbase + 2u * (AV_AH + (arow + mt*16) * SPAD + k0 + acol8));
                ldm_x4(aL[mt], sbase + 2u * (AV_AL + (arow + mt*16) * SPAD + k0 + acol8));
            }
#pragma unroll
            for (int nt = 0; nt < 2; nt++) {
                ldm_x2(bH[nt], sbase + 2u * (AV_VH + (brow + nt*8) * SPAD + k0 + bcol8));
                ldm_x2(bL[nt], sbase + 2u * (AV_VL + (brow + nt*8) * SPAD + k0 + bcol8));
            }
#pragma unroll
            for (int mt = 0; mt < 4; mt++)
#pragma unroll
                for (int nt = 0; nt < 2; nt++) {
                    mma16816(acc[mt][nt], aH[mt], bH[nt]);
                    mma16816(acc[mt][nt], aH[mt], bL[nt]);
                    mma16816(acc[mt][nt], aL[mt], bH[nt]);
                }
        }
        __syncthreads();
    }

    // Epilogue -> g_Hd [bh][s][d] fp32
    const int orow = m0 + warp_m * 64 + (lane >> 2);
    const int ocb0 = warp_n * 16 + (lane & 3) * 2;
#pragma unroll
    for (int mt = 0; mt < 4; mt++) {
        const int r0 = orow + mt * 16;
        const int r1 = r0 + 8;
        float* h0 = g_Hd + ((size_t)bh * SS + r0) * DH;
        float* h1 = g_Hd + ((size_t)bh * SS + r1) * DH;
#pragma unroll
        for (int nt = 0; nt < 2; nt++) {
            const int cb = ocb0 + nt * 8;
            *(float2*)(h0 + cb) = make_float2(acc[mt][nt][0], acc[mt][nt][1]);
            *(float2*)(h1 + cb) = make_float2(acc[mt][nt][2], acc[mt][nt][3]);
        }
    }
}

// ---------------------------------------------------------------------------
// Kernel 5: output projection  out = Hd(reinterleaved) @ Wo^T + bo
// ---------------------------------------------------------------------------
__global__ __launch_bounds__(256, 2)
void oproj_kernel(const float* __restrict__ Wo, const float* __restrict__ bo,
                  float* __restrict__ out)
{
    __shared__ float As[8][128];
    __shared__ float Bs[8][128];

    const int t   = threadIdx.x;
    const int m0  = blockIdx.y * 128;
    const int n0  = blockIdx.x * 128;
    const int row = t >> 1;
    const int seg = t & 1;
    const int tx  = t & 15;
    const int ty  = t >> 4;

    float acc[8][8];
#pragma unroll
    for (int i = 0; i < 8; i++)
#pragma unroll
        for (int j = 0; j < 8; j++) acc[i][j] = 0.f;

    const int m  = m0 + row;
    const int b_ = m / SS;
    const int s_ = m % SS;

    for (int k0 = 0; k0 < DM; k0 += 8) {
        const int j0 = k0 + seg * 4;
        const int h  = j0 >> 6, d = j0 & 63;
        float4 av = *(const float4*)(g_Hd + (((size_t)(b_*Hh + h) * SS) + s_) * DH + d);
        float4 bv = *(const float4*)(Wo + (size_t)(n0 + row) * DM + j0);
        As[seg*4+0][row] = av.x; As[seg*4+1][row] = av.y;
        As[seg*4+2][row] = av.z; As[seg*4+3][row] = av.w;
        Bs[seg*4+0][row] = bv.x; Bs[seg*4+1][row] = bv.y;
        Bs[seg*4+2][row] = bv.z; Bs[seg*4+3][row] = bv.w;
        __syncthreads();
#pragma unroll
        for (int kk = 0; kk < 8; kk++) {
            float a[8], b[8];
#pragma unroll
            for (int i = 0; i < 8; i++) a[i] = As[kk][ty*8 + i];
#pragma unroll
            for (int j = 0; j < 8; j++) b[j] = Bs[kk][tx*8 + j];
#pragma unroll
            for (int i = 0; i < 8; i++)
#pragma unroll
                for (int j = 0; j < 8; j++) acc[i][j] += a[i] * b[j];
        }
        __syncthreads();
    }

#pragma unroll
    for (int i = 0; i < 8; i++) {
        const int mm = m0 + ty*8 + i;
#pragma unroll
        for (int j = 0; j < 8; j++) {
            const int n = n0 + tx*8 + j;
            out[(size_t)mm * DM + n] = acc[i][j] + bo[n];
        }
    }
}

// ---------------------------------------------------------------------------
extern "C" void kernel_launch(void* const* d_in, const int* in_sizes, int n_in,
                              void* d_out, int out_size)
{
    const float* queries = (const float*)d_in[0];
    const float* keys    = (const float*)d_in[1];
    const float* values  = (const float*)d_in[2];
    const float* mask    = (const float*)d_in[3];
    const float* Wq      = (const float*)d_in[4];
    const float* bq      = (const float*)d_in[5];
    const float* Wk      = (const float*)d_in[6];
    const float* bk      = (const float*)d_in[7];
    const float* Wv      = (const float*)d_in[8];
    const float* bv      = (const float*)d_in[9];
    const float* Wo      = (const float*)d_in[10];
    const float* bo      = (const float*)d_in[11];

    float* out = (float*)d_out;            // [4, 2048, 512]
    float* att = out + OUT_ELEMS;          // [4, 8, 2048, 2048]

    cudaFuncSetAttribute(scores_mma_kernel,
                         cudaFuncAttributeMaxDynamicSharedMemorySize, SCORES_SMEM);
    cudaFuncSetAttribute(av_mma_kernel,
                         cudaFuncAttributeMaxDynamicSharedMemorySize, AV_SMEM);

    dim3 projGrid(DM / 128, MQ / 128);     // (4, 64)
    proj_kernel<<<projGrid, 256>>>(queries, Wq, bq, 0);
    proj_kernel<<<projGrid, 256>>>(keys,    Wk, bk, 1);
    proj_kernel<<<projGrid, 256>>>(values,  Wv, bv, 2);

    dim3 scoreGrid(SS / 128, SS / 128, BHN);  // (16, 16, 32)
    scores_mma_kernel<<<scoreGrid, 256, SCORES_SMEM>>>(mask, att);

    softmax_kernel<<<BHN * SS, 256>>>(att);

    dim3 avGrid(SS / 128, BHN);            // (16, 32)
    av_mma_kernel<<<avGrid, 256, AV_SMEM>>>(att);

    dim3 oGrid(DM / 128, MQ / 128);        // (4, 64)
    oproj_kernel<<<oGrid, 256>>>(Wo, bo, out);
}

// round 7
// speedup vs baseline: 1.8048x; 1.2222x over previous
#include <cuda_runtime.h>
#include <cuda_bf16.h>
#include <cstdint>
#include <cstddef>

// Problem constants
#define Hh      8
#define SS      2048
#define DM      512
#define DH      64
#define BATCH   4
#define BHN     (BATCH * Hh)          // 32
#define MQ      (BATCH * SS)          // 8192
#define OUT_ELEMS ((size_t)BATCH * SS * DM)  // 4194304
#define NXBLK   (SS / 128)            // 16 key-tile blocks per row

// Scratch (allocation-free: __device__ globals).
__device__ __nv_bfloat16 g_Qh [BHN * SS * DH];
__device__ __nv_bfloat16 g_Ql [BHN * SS * DH];
__device__ __nv_bfloat16 g_Kh [BHN * SS * DH];
__device__ __nv_bfloat16 g_Kl [BHN * SS * DH];
__device__ __nv_bfloat16 g_Vth[BHN * DH * SS];   // V^T hi: [bh][d][s]
__device__ __nv_bfloat16 g_Vtl[BHN * DH * SS];   // V^T lo
__device__ __nv_bfloat16 g_Hh [BHN * SS * DH];   // attn-out hi: [bh][s][d]
__device__ __nv_bfloat16 g_Hl [BHN * SS * DH];   // attn-out lo
__device__ float2 g_stats [(size_t)BHN * SS * NXBLK]; // per-(row, kblock) {M, S}
__device__ float2 g_rowMS [(size_t)BHN * SS];         // per-row {M, 1/S}

// ===========================================================================
// Warp-level MMA helpers (sm_80-compatible PTX)
// ===========================================================================
__device__ __forceinline__ uint32_t smem_u32(const void* p) {
    uint32_t a;
    asm("{ .reg .u64 t; cvta.to.shared.u64 t, %1; cvt.u32.u64 %0, t; }"
        : "=r"(a) : "l"(p));
    return a;
}
__device__ __forceinline__ void mma16816(float* c, const uint32_t* a, const uint32_t* b) {
    asm volatile(
        "mma.sync.aligned.m16n8k16.row.col.f32.bf16.bf16.f32 "
        "{%0,%1,%2,%3}, {%4,%5,%6,%7}, {%8,%9}, {%0,%1,%2,%3};"
        : "+f"(c[0]), "+f"(c[1]), "+f"(c[2]), "+f"(c[3])
        : "r"(a[0]), "r"(a[1]), "r"(a[2]), "r"(a[3]), "r"(b[0]), "r"(b[1]));
}
__device__ __forceinline__ void ldm_x4(uint32_t* r, uint32_t addr) {
    asm volatile("ldmatrix.sync.aligned.m8n8.x4.shared.b16 {%0,%1,%2,%3}, [%4];"
        : "=r"(r[0]), "=r"(r[1]), "=r"(r[2]), "=r"(r[3]) : "r"(addr));
}
__device__ __forceinline__ void ldm_x2(uint32_t* r, uint32_t addr) {
    asm volatile("ldmatrix.sync.aligned.m8n8.x2.shared.b16 {%0,%1}, [%2];"
        : "=r"(r[0]), "=r"(r[1]) : "r"(addr));
}
__device__ __forceinline__ void split_bf16(float v, __nv_bfloat16& h, __nv_bfloat16& l) {
    h = __float2bfloat16(v);
    l = __float2bfloat16(v - __bfloat162float(h));
}

#define SPAD  72    // operand row pitch in bf16 elems (144B), conflict-free ldmatrix
#define FPITCH 132  // fp32 epilogue staging pitch (floats)

// smem tile offsets (bf16 elems) for 4-operand kernels
#define T_AH 0
#define T_AL (128 * SPAD)
#define T_BH (2 * 128 * SPAD)
#define T_BL (3 * 128 * SPAD)
#define OPER_SMEM (4 * 128 * SPAD * 2)    // 73728 B

// av smem offsets
#define AV_AH 0
#define AV_AL (128 * SPAD)
#define AV_VH (2 * 128 * SPAD)
#define AV_VL (2 * 128 * SPAD + 64 * SPAD)
#define AV_SMEM ((2 * 128 * SPAD + 2 * 64 * SPAD) * 2)   // 55296 B

// ---------------------------------------------------------------------------
// Kernel 1: projection via mma.sync, compensated hi/lo on both operands.
// C = X @ W^T + b.  which: 0->Q, 1->K (both [bh][s][d] hi/lo), 2->V^T ([bh][d][s])
// grid (4, 64), block 256 (8 warps: 2 x 4, each m64 x n32)
// ---------------------------------------------------------------------------
__global__ __launch_bounds__(256)
void proj_mma_kernel(const float* __restrict__ X, const float* __restrict__ W,
                     const float* __restrict__ bias, int which)
{
    extern __shared__ __nv_bfloat16 sm[];
    const int t    = threadIdx.x;
    const int wid  = t >> 5;
    const int lane = t & 31;
    const int m0   = blockIdx.y * 128;
    const int n0   = blockIdx.x * 128;

    const uint32_t sbase = smem_u32(sm);
    const int warp_m = wid >> 2;
    const int warp_n = wid & 3;

    float acc[4][4][4];
#pragma unroll
    for (int mt = 0; mt < 4; mt++)
#pragma unroll
        for (int nt = 0; nt < 4; nt++)
#pragma unroll
            for (int e = 0; e < 4; e++) acc[mt][nt][e] = 0.f;

    const int l16   = lane & 15;
    const int arow  = warp_m * 64 + (lane & 15);
    const int acol8 = (lane >> 4) * 8;
    const int brow  = warp_n * 32 + (l16 & 7);
    const int bcol8 = (l16 >> 3) * 8;

    // loader mapping: 16 threads per row, 1 float4 each, 8 passes
    const int lr_base = t >> 4;     // 0..15
    const int lcol    = (t & 15) * 4;

    for (int kb = 0; kb < DM; kb += 64) {
#pragma unroll
        for (int p = 0; p < 8; p++) {
            const int row = lr_base + p * 16;
            float4 xv = *(const float4*)(X + (size_t)(m0 + row) * DM + kb + lcol);
            float4 wv = *(const float4*)(W + (size_t)(n0 + row) * DM + kb + lcol);
            __nv_bfloat16 h0,h1,h2,h3,l0,l1,l2,l3;
            split_bf16(xv.x,h0,l0); split_bf16(xv.y,h1,l1);
            split_bf16(xv.z,h2,l2); split_bf16(xv.w,h3,l3);
            __nv_bfloat162* pa = (__nv_bfloat162*)(sm + T_AH + row * SPAD + lcol);
            pa[0] = __nv_bfloat162(h0,h1); pa[1] = __nv_bfloat162(h2,h3);
            __nv_bfloat162* qa = (__nv_bfloat162*)(sm + T_AL + row * SPAD + lcol);
            qa[0] = __nv_bfloat162(l0,l1); qa[1] = __nv_bfloat162(l2,l3);
            split_bf16(wv.x,h0,l0); split_bf16(wv.y,h1,l1);
            split_bf16(wv.z,h2,l2); split_bf16(wv.w,h3,l3);
            __nv_bfloat162* pb = (__nv_bfloat162*)(sm + T_BH + row * SPAD + lcol);
            pb[0] = __nv_bfloat162(h0,h1); pb[1] = __nv_bfloat162(h2,h3);
            __nv_bfloat162* qb = (__nv_bfloat162*)(sm + T_BL + row * SPAD + lcol);
            qb[0] = __nv_bfloat162(l0,l1); qb[1] = __nv_bfloat162(l2,l3);
        }
        __syncthreads();

#pragma unroll
        for (int c = 0; c < 3; c++) {
            const int Aoff = (c < 2) ? T_AH : T_AL;
            const int Boff = (c == 1) ? T_BL : T_BH;
#pragma unroll
            for (int ks = 0; ks < 4; ks++) {
                const int k0 = ks * 16;
                uint32_t a[4][4], b[4][2];
#pragma unroll
                for (int mt = 0; mt < 4; mt++)
                    ldm_x4(a[mt], sbase + 2u * (Aoff + (arow + mt*16) * SPAD + k0 + acol8));
#pragma unroll
                for (int nt = 0; nt < 4; nt++)
                    ldm_x2(b[nt], sbase + 2u * (Boff + (brow + nt*8) * SPAD + k0 + bcol8));
#pragma unroll
                for (int mt = 0; mt < 4; mt++)
#pragma unroll
                    for (int nt = 0; nt < 4; nt++)
                        mma16816(acc[mt][nt], a[mt], b[nt]);
            }
        }
        __syncthreads();
    }

    // Epilogue: bias add + hi/lo split + scatter per `which`
    const int b_  = m0 >> 11;                     // batch (m-tile within one batch)
    const int lr0 = warp_m * 64 + (lane >> 2);
    const int cb0 = warp_n * 32 + (lane & 3) * 2;
#pragma unroll
    for (int mt = 0; mt < 4; mt++) {
#pragma unroll
        for (int rr = 0; rr < 2; rr++) {
            const int s_ = (m0 & 2047) + lr0 + mt * 16 + rr * 8;
#pragma unroll
            for (int nt = 0; nt < 4; nt++) {
                const int n  = n0 + cb0 + nt * 8;
                const int h  = n >> 6, d = n & 63;
                const int bh = b_ * Hh + h;
                const float v0 = acc[mt][nt][rr*2+0] + bias[n];
                const float v1 = acc[mt][nt][rr*2+1] + bias[n+1];
                __nv_bfloat16 h0,h1,l0,l1;
                split_bf16(v0,h0,l0); split_bf16(v1,h1,l1);
                if (which == 2) {
                    const size_t i0 = ((size_t)bh * DH + d) * SS + s_;
                    const size_t i1 = ((size_t)bh * DH + d + 1) * SS + s_;
                    g_Vth[i0] = h0; g_Vtl[i0] = l0;
                    g_Vth[i1] = h1; g_Vtl[i1] = l1;
                } else {
                    const size_t idx = ((size_t)bh * SS + s_) * DH + d;
                    if (which == 0) {
                        *(__nv_bfloat162*)(g_Qh + idx) = __nv_bfloat162(h0,h1);
                        *(__nv_bfloat162*)(g_Ql + idx) = __nv_bfloat162(l0,l1);
                    } else {
                        *(__nv_bfloat162*)(g_Kh + idx) = __nv_bfloat162(h0,h1);
                        *(__nv_bfloat162*)(g_Kl + idx) = __nv_bfloat162(l0,l1);
                    }
                }
            }
        }
    }
}

// ---------------------------------------------------------------------------
// Kernel 2: scores via mma.sync + coalesced smem-staged epilogue + softmax stats.
// x = (QK^T)*0.125 + mask -> att (raw); per-(row,128-block) online {M, S} -> g_stats
// grid (16, 16, 32), block 256
// ---------------------------------------------------------------------------
__global__ __launch_bounds__(256)
void scores_mma_kernel(const float* __restrict__ mask, float* __restrict__ att)
{
    extern __shared__ __nv_bfloat16 sm[];
    const int t    = threadIdx.x;
    const int wid  = t >> 5;
    const int lane = t & 31;

    const int bh = blockIdx.z;
    const int m0 = blockIdx.y * 128;
    const int n0 = blockIdx.x * 128;

    // operand load: 8 threads/row, 1 uint4 (8 bf16) each, 4 arrays, 4 passes
    {
        const size_t rb = (size_t)bh * SS * DH;
        const int qi = t & 7;
#pragma unroll
        for (int p = 0; p < 4; p++) {
            const int row = (t >> 3) + p * 32;
            const size_t qoff = rb + (size_t)(m0 + row) * DH + qi * 8;
            const size_t koff = rb + (size_t)(n0 + row) * DH + qi * 8;
            *(uint4*)(sm + T_AH + row * SPAD + qi * 8) = *(const uint4*)(g_Qh + qoff);
            *(uint4*)(sm + T_AL + row * SPAD + qi * 8) = *(const uint4*)(g_Ql + qoff);
            *(uint4*)(sm + T_BH + row * SPAD + qi * 8) = *(const uint4*)(g_Kh + koff);
            *(uint4*)(sm + T_BL + row * SPAD + qi * 8) = *(const uint4*)(g_Kl + koff);
        }
    }
    __syncthreads();

    const uint32_t sbase = smem_u32(sm);
    const int warp_m = wid >> 2;
    const int warp_n = wid & 3;

    float acc[4][4][4];
#pragma unroll
    for (int mt = 0; mt < 4; mt++)
#pragma unroll
        for (int nt = 0; nt < 4; nt++)
#pragma unroll
            for (int e = 0; e < 4; e++) acc[mt][nt][e] = 0.f;

    const int l16   = lane & 15;
    const int arow  = warp_m * 64 + (lane & 15);
    const int acol8 = (lane >> 4) * 8;
    const int brow  = warp_n * 32 + (l16 & 7);
    const int bcol8 = (l16 >> 3) * 8;

#pragma unroll
    for (int c = 0; c < 3; c++) {
        const int Aoff = (c < 2) ? T_AH : T_AL;
        const int Boff = (c == 1) ? T_BL : T_BH;
#pragma unroll
        for (int ks = 0; ks < 4; ks++) {
            const int k0 = ks * 16;
            uint32_t a[4][4], b[4][2];
#pragma unroll
            for (int mt = 0; mt < 4; mt++)
                ldm_x4(a[mt], sbase + 2u * (Aoff + (arow + mt*16) * SPAD + k0 + acol8));
#pragma unroll
            for (int nt = 0; nt < 4; nt++)
                ldm_x2(b[nt], sbase + 2u * (Boff + (brow + nt*8) * SPAD + k0 + bcol8));
#pragma unroll
            for (int mt = 0; mt < 4; mt++)
#pragma unroll
                for (int nt = 0; nt < 4; nt++)
                    mma16816(acc[mt][nt], a[mt], b[nt]);
        }
    }

    // Stage scaled accumulators into fp32 smem (pitch 132)
    __syncthreads();
    float* smf = (float*)sm;
    {
        const int lr0 = warp_m * 64 + (lane >> 2);
        const int cb0 = warp_n * 32 + (lane & 3) * 2;
#pragma unroll
        for (int mt = 0; mt < 4; mt++) {
            const int r0 = lr0 + mt * 16;
#pragma unroll
            for (int nt = 0; nt < 4; nt++) {
                const int cb = cb0 + nt * 8;
                *(float2*)(smf + (size_t)r0 * FPITCH + cb) =
                    make_float2(acc[mt][nt][0] * 0.125f, acc[mt][nt][1] * 0.125f);
                *(float2*)(smf + (size_t)(r0 + 8) * FPITCH + cb) =
                    make_float2(acc[mt][nt][2] * 0.125f, acc[mt][nt][3] * 0.125f);
            }
        }
    }
    __syncthreads();

    // Coalesced store + mask + per-row softmax partials.
    // 16 threads/row, 2 float4 each (cols c, c+64), 8 passes.
    {
        const int lrb = t >> 4;          // 0..15
        const int c0  = (t & 15) * 4;    // 0..60
#pragma unroll
        for (int p = 0; p < 8; p++) {
            const int row  = lrb + p * 16;
            const int grow = m0 + row;
            float4 v0 = *(float4*)(smf + (size_t)row * FPITCH + c0);
            float4 v1 = *(float4*)(smf + (size_t)row * FPITCH + c0 + 64);
            float4 k0 = *(const float4*)(mask + (size_t)grow * SS + n0 + c0);
            float4 k1 = *(const float4*)(mask + (size_t)grow * SS + n0 + c0 + 64);
            v0.x += k0.x; v0.y += k0.y; v0.z += k0.z; v0.w += k0.w;
            v1.x += k1.x; v1.y += k1.y; v1.z += k1.z; v1.w += k1.w;
            float* arow_p = att + ((size_t)bh * SS + grow) * SS + n0;
            *(float4*)(arow_p + c0)      = v0;
            *(float4*)(arow_p + c0 + 64) = v1;
            // stats over this thread's 8 values, then 16-lane reduction
            float mx = fmaxf(fmaxf(fmaxf(v0.x, v0.y), fmaxf(v0.z, v0.w)),
                             fmaxf(fmaxf(v1.x, v1.y), fmaxf(v1.z, v1.w)));
#pragma unroll
            for (int off = 1; off < 16; off <<= 1)
                mx = fmaxf(mx, __shfl_xor_sync(0xFFFFFFFFu, mx, off));
            float s = expf(v0.x - mx) + expf(v0.y - mx) + expf(v0.z - mx) + expf(v0.w - mx)
                    + expf(v1.x - mx) + expf(v1.y - mx) + expf(v1.z - mx) + expf(v1.w - mx);
#pragma unroll
            for (int off = 1; off < 16; off <<= 1)
                s += __shfl_xor_sync(0xFFFFFFFFu, s, off);
            if ((t & 15) == 0)
                g_stats[((size_t)bh * SS + grow) * NXBLK + blockIdx.x] = make_float2(mx, s);
        }
    }
}

// ---------------------------------------------------------------------------
// Kernel 3: reduce per-row partials -> {M, 1/S}
// grid 256, block 256  (65536 rows)
// ---------------------------------------------------------------------------
__global__ __launch_bounds__(256)
void reduce_stats_kernel()
{
    const size_t r = (size_t)blockIdx.x * 256 + threadIdx.x;
    const float2* p = g_stats + r * NXBLK;
    float2 loc[NXBLK];
#pragma unroll
    for (int i = 0; i < NXBLK; i++) loc[i] = p[i];
    float M = loc[0].x;
#pragma unroll
    for (int i = 1; i < NXBLK; i++) M = fmaxf(M, loc[i].x);
    float S = 0.f;
#pragma unroll
    for (int i = 0; i < NXBLK; i++) S += loc[i].y * expf(loc[i].x - M);
    g_rowMS[r] = make_float2(M, 1.0f / S);
}

// ---------------------------------------------------------------------------
// Kernel 4: av = softmax-normalize (writes att) + PV GEMM -> g_Hh/g_Hl.
// grid (16, 32): x = m-tile(128), y = bh. block 256 (8 warps: 2 x 4 -> m64 x n16)
// ---------------------------------------------------------------------------
__global__ __launch_bounds__(256)
void av_mma_kernel(float* __restrict__ att)
{
    extern __shared__ __nv_bfloat16 sm[];
    const int t    = threadIdx.x;
    const int wid  = t >> 5;
    const int lane = t & 31;

    const int bh = blockIdx.y;
    const int m0 = blockIdx.x * 128;

    const uint32_t sbase = smem_u32(sm);
    const int warp_m = wid >> 2;
    const int warp_n = wid & 3;

    float acc[4][2][4];
#pragma unroll
    for (int mt = 0; mt < 4; mt++)
#pragma unroll
        for (int nt = 0; nt < 2; nt++)
#pragma unroll
            for (int e = 0; e < 4; e++) acc[mt][nt][e] = 0.f;

    const int l16   = lane & 15;
    const int arow  = warp_m * 64 + (lane & 15);
    const int acol8 = (lane >> 4) * 8;
    const int brow  = warp_n * 16 + (l16 & 7);
    const int bcol8 = (l16 >> 3) * 8;

    // loader mappings
    const int lrb = t >> 4;          // att: 16 threads/row
    const int c0  = (t & 15) * 4;
    const int vqi = t & 7;           // V: 8 threads/row

    // preload row stats for the 8 rows this thread normalizes
    float2 ms[8];
#pragma unroll
    for (int p = 0; p < 8; p++)
        ms[p] = g_rowMS[(size_t)bh * SS + m0 + lrb + p * 16];

    for (int kb = 0; kb < SS; kb += 64) {
        // att chunk: normalize + write back + hi/lo split into smem
#pragma unroll
        for (int p = 0; p < 8; p++) {
            const int row = lrb + p * 16;
            float* ap = att + ((size_t)bh * SS + m0 + row) * SS + kb + c0;
            float4 v = *(const float4*)ap;
            const float M = ms[p].x, inv = ms[p].y;
            v.x = expf(v.x - M) * inv;
            v.y = expf(v.y - M) * inv;
            v.z = expf(v.z - M) * inv;
            v.w = expf(v.w - M) * inv;
            *(float4*)ap = v;
            __nv_bfloat16 h0,h1,h2,h3,l0,l1,l2,l3;
            split_bf16(v.x,h0,l0); split_bf16(v.y,h1,l1);
            split_bf16(v.z,h2,l2); split_bf16(v.w,h3,l3);
            __nv_bfloat162* ph = (__nv_bfloat162*)(sm + AV_AH + row * SPAD + c0);
            ph[0] = __nv_bfloat162(h0,h1); ph[1] = __nv_bfloat162(h2,h3);
            __nv_bfloat162* pl = (__nv_bfloat162*)(sm + AV_AL + row * SPAD + c0);
            pl[0] = __nv_bfloat162(l0,l1); pl[1] = __nv_bfloat162(l2,l3);
        }
        // V^T chunk: 64 d-rows x 64 s-cols bf16, 8 threads/row, 2 passes
#pragma unroll
        for (int p = 0; p < 2; p++) {
            const int vr = (t >> 3) + p * 32;
            const size_t voff = ((size_t)bh * DH + vr) * SS + kb + vqi * 8;
            *(uint4*)(sm + AV_VH + vr * SPAD + vqi * 8) = *(const uint4*)(g_Vth + voff);
            *(uint4*)(sm + AV_VL + vr * SPAD + vqi * 8) = *(const uint4*)(g_Vtl + voff);
        }
        __syncthreads();

#pragma unroll
        for (int ks = 0; ks < 4; ks++) {
            const int k0 = ks * 16;
            uint32_t aH[4][4], aL[4][4], bH[2][2], bL[2][2];
#pragma unroll
            for (int mt = 0; mt < 4; mt++) {
                ldm_x4(aH[mt], sbase + 2u * (AV_AH + (arow + mt*16) * SPAD + k0 + acol8));
                ldm_x4(aL[mt], sbase + 2u * (AV_AL + (arow + mt*16) * SPAD + k0 + acol8));
            }
#pragma unroll
            for (int nt = 0; nt < 2; nt++) {
                ldm_x2(bH[nt], sbase + 2u * (AV_VH + (brow + nt*8) * SPAD + k0 + bcol8));
                ldm_x2(bL[nt], sbase + 2u * (AV_VL + (brow + nt*8) * SPAD + k0 + bcol8));
            }
#pragma unroll
            for (int mt = 0; mt < 4; mt++)
#pragma unroll
                for (int nt = 0; nt < 2; nt++) {
                    mma16816(acc[mt][nt], aH[mt], bH[nt]);
                    mma16816(acc[mt][nt], aH[mt], bL[nt]);
                    mma16816(acc[mt][nt], aL[mt], bH[nt]);
                }
        }
        __syncthreads();
    }

    // Epilogue -> g_Hh/g_Hl bf16 hi/lo, [bh][s][d]
    const int orow = m0 + warp_m * 64 + (lane >> 2);
    const int ocb0 = warp_n * 16 + (lane & 3) * 2;
#pragma unroll
    for (int mt = 0; mt < 4; mt++) {
#pragma unroll
        for (int rr = 0; rr < 2; rr++) {
            const int r = orow + mt * 16 + rr * 8;
#pragma unroll
            for (int nt = 0; nt < 2; nt++) {
                const int cb = ocb0 + nt * 8;
                const float v0 = acc[mt][nt][rr*2+0];
                const float v1 = acc[mt][nt][rr*2+1];
                __nv_bfloat16 h0,h1,l0,l1;
                split_bf16(v0,h0,l0); split_bf16(v1,h1,l1);
                const size_t idx = ((size_t)bh * SS + r) * DH + cb;
                *(__nv_bfloat162*)(g_Hh + idx) = __nv_bfloat162(h0,h1);
                *(__nv_bfloat162*)(g_Hl + idx) = __nv_bfloat162(l0,l1);
            }
        }
    }
}

// ---------------------------------------------------------------------------
// Kernel 5: output projection via mma.sync: out = H @ Wo^T + bo.
// H hi/lo already bf16 in [bh][s][d]; k-block kb = head index.
// grid (4, 64), block 256
// ---------------------------------------------------------------------------
__global__ __launch_bounds__(256)
void oproj_mma_kernel(const float* __restrict__ Wo, const float* __restrict__ bo,
                      float* __restrict__ out)
{
    extern __shared__ __nv_bfloat16 sm[];
    const int t    = threadIdx.x;
    const int wid  = t >> 5;
    const int lane = t & 31;
    const int m0   = blockIdx.y * 128;
    const int n0   = blockIdx.x * 128;
    const int b_   = m0 >> 11;
    const int s0   = m0 & 2047;

    const uint32_t sbase = smem_u32(sm);
    const int warp_m = wid >> 2;
    const int warp_n = wid & 3;

    float acc[4][4][4];
#pragma unroll
    for (int mt = 0; mt < 4; mt++)
#pragma unroll
        for (int nt = 0; nt < 4; nt++)
#pragma unroll
            for (int e = 0; e < 4; e++) acc[mt][nt][e] = 0.f;

    const int l16   = lane & 15;
    const int arow  = warp_m * 64 + (lane & 15);
    const int acol8 = (lane >> 4) * 8;
    const int brow  = warp_n * 32 + (l16 & 7);
    const int bcol8 = (l16 >> 3) * 8;

    const int aqi = t & 7;          // A: 8 threads/row (bf16 rows of 128B)
    const int wlr = t >> 4;         // B: 16 threads/row (fp32)
    const int wc0 = (t & 15) * 4;

    for (int kb = 0; kb < 8; kb++) {
        // A: H hi/lo tiles, direct bf16 copy
#pragma unroll
        for (int p = 0; p < 4; p++) {
            const int row = (t >> 3) + p * 32;
            const size_t hoff = (((size_t)(b_ * Hh + kb) * SS) + s0 + row) * DH + aqi * 8;
            *(uint4*)(sm + T_AH + row * SPAD + aqi * 8) = *(const uint4*)(g_Hh + hoff);
            *(uint4*)(sm + T_AL + row * SPAD + aqi * 8) = *(const uint4*)(g_Hl + hoff);
        }
        // B: Wo fp32 -> hi/lo split
#pragma unroll
        for (int p = 0; p < 8; p++) {
            const int row = wlr + p * 16;
            float4 wv = *(const float4*)(Wo + (size_t)(n0 + row) * DM + kb * 64 + wc0);
            __nv_bfloat16 h0,h1,h2,h3,l0,l1,l2,l3;
            split_bf16(wv.x,h0,l0); split_bf16(wv.y,h1,l1);
            split_bf16(wv.z,h2,l2); split_bf16(wv.w,h3,l3);
            __nv_bfloat162* pb = (__nv_bfloat162*)(sm + T_BH + row * SPAD + wc0);
            pb[0] = __nv_bfloat162(h0,h1); pb[1] = __nv_bfloat162(h2,h3);
            __nv_bfloat162* qb = (__nv_bfloat162*)(sm + T_BL + row * SPAD + wc0);
            qb[0] = __nv_bfloat162(l0,l1); qb[1] = __nv_bfloat162(l2,l3);
        }
        __syncthreads();

#pragma unroll
        for (int c = 0; c < 3; c++) {
            const int Aoff = (c < 2) ? T_AH : T_AL;
            const int Boff = (c == 1) ? T_BL : T_BH;
#pragma unroll
            for (int ks = 0; ks < 4; ks++) {
                const int k0 = ks * 16;
                uint32_t a[4][4], b[4][2];
#pragma unroll
                for (int mt = 0; mt < 4; mt++)
                    ldm_x4(a[mt], sbase + 2u * (Aoff + (arow + mt*16) * SPAD + k0 + acol8));
#pragma unroll
                for (int nt = 0; nt < 4; nt++)
                    ldm_x2(b[nt], sbase + 2u * (Boff + (brow + nt*8) * SPAD + k0 + bcol8));
#pragma unroll
                for (int mt = 0; mt < 4; mt++)
#pragma unroll
                    for (int nt = 0; nt < 4; nt++)
                        mma16816(acc[mt][nt], a[mt], b[nt]);
            }
        }
        __syncthreads();
    }

    // Epilogue: + bias -> out fp32
    const int lr0 = warp_m * 64 + (lane >> 2);
    const int cb0 = warp_n * 32 + (lane & 3) * 2;
#pragma unroll
    for (int mt = 0; mt < 4; mt++) {
#pragma unroll
        for (int rr = 0; rr < 2; rr++) {
            const int mm = m0 + lr0 + mt * 16 + rr * 8;
#pragma unroll
            for (int nt = 0; nt < 4; nt++) {
                const int n = n0 + cb0 + nt * 8;
                *(float2*)(out + (size_t)mm * DM + n) =
                    make_float2(acc[mt][nt][rr*2+0] + bo[n],
                                acc[mt][nt][rr*2+1] + bo[n+1]);
            }
        }
    }
}

// ---------------------------------------------------------------------------
extern "C" void kernel_launch(void* const* d_in, const int* in_sizes, int n_in,
                              void* d_out, int out_size)
{
    const float* queries = (const float*)d_in[0];
    const float* keys    = (const float*)d_in[1];
    const float* values  = (const float*)d_in[2];
    const float* mask    = (const float*)d_in[3];
    const float* Wq      = (const float*)d_in[4];
    const float* bq      = (const float*)d_in[5];
    const float* Wk      = (const float*)d_in[6];
    const float* bk      = (const float*)d_in[7];
    const float* Wv      = (const float*)d_in[8];
    const float* bv      = (const float*)d_in[9];
    const float* Wo      = (const float*)d_in[10];
    const float* bo      = (const float*)d_in[11];

    float* out = (float*)d_out;            // [4, 2048, 512]
    float* att = out + OUT_ELEMS;          // [4, 8, 2048, 2048]

    cudaFuncSetAttribute(proj_mma_kernel,
                         cudaFuncAttributeMaxDynamicSharedMemorySize, OPER_SMEM);
    cudaFuncSetAttribute(scores_mma_kernel,
                         cudaFuncAttributeMaxDynamicSharedMemorySize, OPER_SMEM);
    cudaFuncSetAttribute(av_mma_kernel,
                         cudaFuncAttributeMaxDynamicSharedMemorySize, AV_SMEM);
    cudaFuncSetAttribute(oproj_mma_kernel,
                         cudaFuncAttributeMaxDynamicSharedMemorySize, OPER_SMEM);

    dim3 projGrid(DM / 128, MQ / 128);     // (4, 64)
    proj_mma_kernel<<<projGrid, 256, OPER_SMEM>>>(queries, Wq, bq, 0);
    proj_mma_kernel<<<projGrid, 256, OPER_SMEM>>>(keys,    Wk, bk, 1);
    proj_mma_kernel<<<projGrid, 256, OPER_SMEM>>>(values,  Wv, bv, 2);

    dim3 scoreGrid(SS / 128, SS / 128, BHN);  // (16, 16, 32)
    scores_mma_kernel<<<scoreGrid, 256, OPER_SMEM>>>(mask, att);

    reduce_stats_kernel<<<(BHN * SS) / 256, 256>>>();

    dim3 avGrid(SS / 128, BHN);            // (16, 32)
    av_mma_kernel<<<avGrid, 256, AV_SMEM>>>(att);

    dim3 oGrid(DM / 128, MQ / 128);        // (4, 64)
    oproj_mma_kernel<<<oGrid, 256, OPER_SMEM>>>(Wo, bo, out);
}

// round 10
// speedup vs baseline: 2.5184x; 1.3954x over previous
#include <cuda_runtime.h>
#include <cuda_bf16.h>
#include <cstdint>
#include <cstddef>

// Problem constants
#define Hh      8
#define SS      2048
#define DM      512
#define DH      64
#define BATCH   4
#define BHN     (BATCH * Hh)          // 32
#define MQ      (BATCH * SS)          // 8192
#define OUT_ELEMS ((size_t)BATCH * SS * DM)  // 4194304
#define NXBLK   (SS / 128)            // 16 key-tile blocks per row

// Scratch (allocation-free: __device__ globals).
__device__ __nv_bfloat16 g_Qh [BHN * SS * DH];
__device__ __nv_bfloat16 g_Ql [BHN * SS * DH];
__device__ __nv_bfloat16 g_Kh [BHN * SS * DH];
__device__ __nv_bfloat16 g_Kl [BHN * SS * DH];
__device__ __nv_bfloat16 g_Vth[BHN * DH * SS];   // V^T hi: [bh][d][s]
__device__ __nv_bfloat16 g_Vtl[BHN * DH * SS];   // V^T lo
__device__ __nv_bfloat16 g_Hh [BHN * SS * DH];   // attn-out hi: [bh][s][d]
__device__ __nv_bfloat16 g_Hl [BHN * SS * DH];   // attn-out lo
__device__ float2 g_stats [(size_t)BHN * SS * NXBLK]; // per-(row, kblock) {M, S}
__device__ float2 g_rowMS [(size_t)BHN * SS];         // per-row {M, 1/S}

// ===========================================================================
// Warp-level MMA helpers (sm_80-compatible PTX)
// ===========================================================================
__device__ __forceinline__ uint32_t smem_u32(const void* p) {
    uint32_t a;
    asm("{ .reg .u64 t; cvta.to.shared.u64 t, %1; cvt.u32.u64 %0, t; }"
        : "=r"(a) : "l"(p));
    return a;
}
__device__ __forceinline__ void mma16816(float* c, const uint32_t* a, const uint32_t* b) {
    asm volatile(
        "mma.sync.aligned.m16n8k16.row.col.f32.bf16.bf16.f32 "
        "{%0,%1,%2,%3}, {%4,%5,%6,%7}, {%8,%9}, {%0,%1,%2,%3};"
        : "+f"(c[0]), "+f"(c[1]), "+f"(c[2]), "+f"(c[3])
        : "r"(a[0]), "r"(a[1]), "r"(a[2]), "r"(a[3]), "r"(b[0]), "r"(b[1]));
}
__device__ __forceinline__ void ldm_x4(uint32_t* r, uint32_t addr) {
    asm volatile("ldmatrix.sync.aligned.m8n8.x4.shared.b16 {%0,%1,%2,%3}, [%4];"
        : "=r"(r[0]), "=r"(r[1]), "=r"(r[2]), "=r"(r[3]) : "r"(addr));
}
__device__ __forceinline__ void ldm_x2(uint32_t* r, uint32_t addr) {
    asm volatile("ldmatrix.sync.aligned.m8n8.x2.shared.b16 {%0,%1}, [%2];"
        : "=r"(r[0]), "=r"(r[1]) : "r"(addr));
}
__device__ __forceinline__ void split_bf16(float v, __nv_bfloat16& h, __nv_bfloat16& l) {
    h = __float2bfloat16(v);
    l = __float2bfloat16(v - __bfloat162float(h));
}

#define SPAD  72    // operand row pitch in bf16 elems (144B), conflict-free ldmatrix
#define FPITCH 132  // fp32 epilogue staging pitch (floats)

// smem tile offsets (bf16 elems) for 4-operand kernels
#define T_AH 0
#define T_AL (128 * SPAD)
#define T_BH (2 * 128 * SPAD)
#define T_BL (3 * 128 * SPAD)
#define OPER_SMEM (4 * 128 * SPAD * 2)    // 73728 B

// av smem offsets
#define AV_AH 0
#define AV_AL (128 * SPAD)
#define AV_VH (2 * 128 * SPAD)
#define AV_VL (2 * 128 * SPAD + 64 * SPAD)
#define AV_SMEM ((2 * 128 * SPAD + 2 * 64 * SPAD) * 2)   // 55296 B

// ---------------------------------------------------------------------------
// Kernel 1: merged QKV projection via mma.sync, compensated hi/lo.
// blockIdx.z: 0->Q, 1->K ([bh][s][d] hi/lo), 2->V^T ([bh][d][s])
// grid (4, 64, 3), block 256 (8 warps: 2 x 4, each m64 x n32)
// ---------------------------------------------------------------------------
__global__ __launch_bounds__(256, 2)
void proj_mma_kernel(const float* __restrict__ Xq, const float* __restrict__ Xk,
                     const float* __restrict__ Xv,
                     const float* __restrict__ Wq, const float* __restrict__ Wk,
                     const float* __restrict__ Wv,
                     const float* __restrict__ bq, const float* __restrict__ bk,
                     const float* __restrict__ bv)
{
    extern __shared__ __nv_bfloat16 sm[];
    const int which = blockIdx.z;
    const float* X    = (which == 0) ? Xq : (which == 1) ? Xk : Xv;
    const float* W    = (which == 0) ? Wq : (which == 1) ? Wk : Wv;
    const float* bias = (which == 0) ? bq : (which == 1) ? bk : bv;

    const int t    = threadIdx.x;
    const int wid  = t >> 5;
    const int lane = t & 31;
    const int m0   = blockIdx.y * 128;
    const int n0   = blockIdx.x * 128;

    const uint32_t sbase = smem_u32(sm);
    const int warp_m = wid >> 2;
    const int warp_n = wid & 3;

    float acc[4][4][4];
#pragma unroll
    for (int mt = 0; mt < 4; mt++)
#pragma unroll
        for (int nt = 0; nt < 4; nt++)
#pragma unroll
            for (int e = 0; e < 4; e++) acc[mt][nt][e] = 0.f;

    const int l16   = lane & 15;
    const int arow  = warp_m * 64 + (lane & 15);
    const int acol8 = (lane >> 4) * 8;
    const int brow  = warp_n * 32 + (l16 & 7);
    const int bcol8 = (l16 >> 3) * 8;

    // loader mapping: 16 threads per row, 1 float4 each, 8 passes
    const int lr_base = t >> 4;     // 0..15
    const int lcol    = (t & 15) * 4;

    for (int kb = 0; kb < DM; kb += 64) {
#pragma unroll
        for (int p = 0; p < 8; p++) {
            const int row = lr_base + p * 16;
            float4 xv = *(const float4*)(X + (size_t)(m0 + row) * DM + kb + lcol);
            float4 wv = *(const float4*)(W + (size_t)(n0 + row) * DM + kb + lcol);
            __nv_bfloat16 h0,h1,h2,h3,l0,l1,l2,l3;
            split_bf16(xv.x,h0,l0); split_bf16(xv.y,h1,l1);
            split_bf16(xv.z,h2,l2); split_bf16(xv.w,h3,l3);
            __nv_bfloat162* pa = (__nv_bfloat162*)(sm + T_AH + row * SPAD + lcol);
            pa[0] = __nv_bfloat162(h0,h1); pa[1] = __nv_bfloat162(h2,h3);
            __nv_bfloat162* qa = (__nv_bfloat162*)(sm + T_AL + row * SPAD + lcol);
            qa[0] = __nv_bfloat162(l0,l1); qa[1] = __nv_bfloat162(l2,l3);
            split_bf16(wv.x,h0,l0); split_bf16(wv.y,h1,l1);
            split_bf16(wv.z,h2,l2); split_bf16(wv.w,h3,l3);
            __nv_bfloat162* pb = (__nv_bfloat162*)(sm + T_BH + row * SPAD + lcol);
            pb[0] = __nv_bfloat162(h0,h1); pb[1] = __nv_bfloat162(h2,h3);
            __nv_bfloat162* qb = (__nv_bfloat162*)(sm + T_BL + row * SPAD + lcol);
            qb[0] = __nv_bfloat162(l0,l1); qb[1] = __nv_bfloat162(l2,l3);
        }
        __syncthreads();

#pragma unroll
        for (int c = 0; c < 3; c++) {
            const int Aoff = (c < 2) ? T_AH : T_AL;
            const int Boff = (c == 1) ? T_BL : T_BH;
#pragma unroll
            for (int ks = 0; ks < 4; ks++) {
                const int k0 = ks * 16;
                uint32_t a[4][4], b[4][2];
#pragma unroll
                for (int mt = 0; mt < 4; mt++)
                    ldm_x4(a[mt], sbase + 2u * (Aoff + (arow + mt*16) * SPAD + k0 + acol8));
#pragma unroll
                for (int nt = 0; nt < 4; nt++)
                    ldm_x2(b[nt], sbase + 2u * (Boff + (brow + nt*8) * SPAD + k0 + bcol8));
#pragma unroll
                for (int mt = 0; mt < 4; mt++)
#pragma unroll
                    for (int nt = 0; nt < 4; nt++)
                        mma16816(acc[mt][nt], a[mt], b[nt]);
            }
        }
        __syncthreads();
    }

    // Epilogue: bias add + hi/lo split + scatter per `which`
    const int b_  = m0 >> 11;
    const int lr0 = warp_m * 64 + (lane >> 2);
    const int cb0 = warp_n * 32 + (lane & 3) * 2;
#pragma unroll
    for (int mt = 0; mt < 4; mt++) {
#pragma unroll
        for (int rr = 0; rr < 2; rr++) {
            const int s_ = (m0 & 2047) + lr0 + mt * 16 + rr * 8;
#pragma unroll
            for (int nt = 0; nt < 4; nt++) {
                const int n  = n0 + cb0 + nt * 8;
                const int h  = n >> 6, d = n & 63;
                const int bh = b_ * Hh + h;
                const float v0 = acc[mt][nt][rr*2+0] + bias[n];
                const float v1 = acc[mt][nt][rr*2+1] + bias[n+1];
                __nv_bfloat16 h0,h1,l0,l1;
                split_bf16(v0,h0,l0); split_bf16(v1,h1,l1);
                if (which == 2) {
                    const size_t i0 = ((size_t)bh * DH + d) * SS + s_;
                    const size_t i1 = ((size_t)bh * DH + d + 1) * SS + s_;
                    g_Vth[i0] = h0; g_Vtl[i0] = l0;
                    g_Vth[i1] = h1; g_Vtl[i1] = l1;
                } else {
                    const size_t idx = ((size_t)bh * SS + s_) * DH + d;
                    if (which == 0) {
                        *(__nv_bfloat162*)(g_Qh + idx) = __nv_bfloat162(h0,h1);
                        *(__nv_bfloat162*)(g_Ql + idx) = __nv_bfloat162(l0,l1);
                    } else {
                        *(__nv_bfloat162*)(g_Kh + idx) = __nv_bfloat162(h0,h1);
                        *(__nv_bfloat162*)(g_Kl + idx) = __nv_bfloat162(l0,l1);
                    }
                }
            }
        }
    }
}

// ---------------------------------------------------------------------------
// Kernel 2: scores via mma.sync + coalesced smem-staged epilogue + softmax stats.
// x = (QK^T)*0.125 + mask -> att (raw); per-(row,128-block) {M, S} -> g_stats
// grid (16, 16, 32), block 256
// ---------------------------------------------------------------------------
__global__ __launch_bounds__(256, 2)
void scores_mma_kernel(const float* __restrict__ mask, float* __restrict__ att)
{
    extern __shared__ __nv_bfloat16 sm[];
    const int t    = threadIdx.x;
    const int wid  = t >> 5;
    const int lane = t & 31;

    const int bh = blockIdx.z;
    const int m0 = blockIdx.y * 128;
    const int n0 = blockIdx.x * 128;

    // operand load: 8 threads/row, 1 uint4 (8 bf16) each, 4 arrays, 4 passes
    {
        const size_t rb = (size_t)bh * SS * DH;
        const int qi = t & 7;
#pragma unroll
        for (int p = 0; p < 4; p++) {
            const int row = (t >> 3) + p * 32;
            const size_t qoff = rb + (size_t)(m0 + row) * DH + qi * 8;
            const size_t koff = rb + (size_t)(n0 + row) * DH + qi * 8;
            *(uint4*)(sm + T_AH + row * SPAD + qi * 8) = *(const uint4*)(g_Qh + qoff);
            *(uint4*)(sm + T_AL + row * SPAD + qi * 8) = *(const uint4*)(g_Ql + qoff);
            *(uint4*)(sm + T_BH + row * SPAD + qi * 8) = *(const uint4*)(g_Kh + koff);
            *(uint4*)(sm + T_BL + row * SPAD + qi * 8) = *(const uint4*)(g_Kl + koff);
        }
    }
    __syncthreads();

    const uint32_t sbase = smem_u32(sm);
    const int warp_m = wid >> 2;
    const int warp_n = wid & 3;

    float acc[4][4][4];
#pragma unroll
    for (int mt = 0; mt < 4; mt++)
#pragma unroll
        for (int nt = 0; nt < 4; nt++)
#pragma unroll
            for (int e = 0; e < 4; e++) acc[mt][nt][e] = 0.f;

    const int l16   = lane & 15;
    const int arow  = warp_m * 64 + (lane & 15);
    const int acol8 = (lane >> 4) * 8;
    const int brow  = warp_n * 32 + (l16 & 7);
    const int bcol8 = (l16 >> 3) * 8;

#pragma unroll
    for (int c = 0; c < 3; c++) {
        const int Aoff = (c < 2) ? T_AH : T_AL;
        const int Boff = (c == 1) ? T_BL : T_BH;
#pragma unroll
        for (int ks = 0; ks < 4; ks++) {
            const int k0 = ks * 16;
            uint32_t a[4][4], b[4][2];
#pragma unroll
            for (int mt = 0; mt < 4; mt++)
                ldm_x4(a[mt], sbase + 2u * (Aoff + (arow + mt*16) * SPAD + k0 + acol8));
#pragma unroll
            for (int nt = 0; nt < 4; nt++)
                ldm_x2(b[nt], sbase + 2u * (Boff + (brow + nt*8) * SPAD + k0 + bcol8));
#pragma unroll
            for (int mt = 0; mt < 4; mt++)
#pragma unroll
                for (int nt = 0; nt < 4; nt++)
                    mma16816(acc[mt][nt], a[mt], b[nt]);
        }
    }

    // Stage scaled accumulators into fp32 smem (pitch 132)
    __syncthreads();
    float* smf = (float*)sm;
    {
        const int lr0 = warp_m * 64 + (lane >> 2);
        const int cb0 = warp_n * 32 + (lane & 3) * 2;
#pragma unroll
        for (int mt = 0; mt < 4; mt++) {
            const int r0 = lr0 + mt * 16;
#pragma unroll
            for (int nt = 0; nt < 4; nt++) {
                const int cb = cb0 + nt * 8;
                *(float2*)(smf + (size_t)r0 * FPITCH + cb) =
                    make_float2(acc[mt][nt][0] * 0.125f, acc[mt][nt][1] * 0.125f);
                *(float2*)(smf + (size_t)(r0 + 8) * FPITCH + cb) =
                    make_float2(acc[mt][nt][2] * 0.125f, acc[mt][nt][3] * 0.125f);
            }
        }
    }
    __syncthreads();

    // Coalesced store + mask + per-row softmax partials.
    {
        const int lrb = t >> 4;          // 0..15
        const int c0  = (t & 15) * 4;    // 0..60
#pragma unroll
        for (int p = 0; p < 8; p++) {
            const int row  = lrb + p * 16;
            const int grow = m0 + row;
            float4 v0 = *(float4*)(smf + (size_t)row * FPITCH + c0);
            float4 v1 = *(float4*)(smf + (size_t)row * FPITCH + c0 + 64);
            float4 k0 = *(const float4*)(mask + (size_t)grow * SS + n0 + c0);
            float4 k1 = *(const float4*)(mask + (size_t)grow * SS + n0 + c0 + 64);
            v0.x += k0.x; v0.y += k0.y; v0.z += k0.z; v0.w += k0.w;
            v1.x += k1.x; v1.y += k1.y; v1.z += k1.z; v1.w += k1.w;
            float* arow_p = att + ((size_t)bh * SS + grow) * SS + n0;
            *(float4*)(arow_p + c0)      = v0;
            *(float4*)(arow_p + c0 + 64) = v1;
            float mx = fmaxf(fmaxf(fmaxf(v0.x, v0.y), fmaxf(v0.z, v0.w)),
                             fmaxf(fmaxf(v1.x, v1.y), fmaxf(v1.z, v1.w)));
#pragma unroll
            for (int off = 1; off < 16; off <<= 1)
                mx = fmaxf(mx, __shfl_xor_sync(0xFFFFFFFFu, mx, off));
            float s = __expf(v0.x - mx) + __expf(v0.y - mx) + __expf(v0.z - mx) + __expf(v0.w - mx)
                    + __expf(v1.x - mx) + __expf(v1.y - mx) + __expf(v1.z - mx) + __expf(v1.w - mx);
#pragma unroll
            for (int off = 1; off < 16; off <<= 1)
                s += __shfl_xor_sync(0xFFFFFFFFu, s, off);
            if ((t & 15) == 0)
                g_stats[((size_t)bh * SS + grow) * NXBLK + blockIdx.x] = make_float2(mx, s);
        }
    }
}

// ---------------------------------------------------------------------------
// Kernel 3: reduce per-row partials -> {M, 1/S}
// grid 256, block 256  (65536 rows)
// ---------------------------------------------------------------------------
__global__ __launch_bounds__(256)
void reduce_stats_kernel()
{
    const size_t r = (size_t)blockIdx.x * 256 + threadIdx.x;
    const float2* p = g_stats + r * NXBLK;
    float2 loc[NXBLK];
#pragma unroll
    for (int i = 0; i < NXBLK; i++) loc[i] = p[i];
    float M = loc[0].x;
#pragma unroll
    for (int i = 1; i < NXBLK; i++) M = fmaxf(M, loc[i].x);
    float S = 0.f;
#pragma unroll
    for (int i = 0; i < NXBLK; i++) S += loc[i].y * __expf(loc[i].x - M);
    g_rowMS[r] = make_float2(M, 1.0f / S);
}

// ---------------------------------------------------------------------------
// Kernel 4: av = softmax-normalize (writes att) + PV GEMM -> g_Hh/g_Hl.
// grid (16, 32): x = m-tile(128), y = bh. block 256 (8 warps: 2 x 4 -> m64 x n16)
// ---------------------------------------------------------------------------
__global__ __launch_bounds__(256, 2)
void av_mma_kernel(float* __restrict__ att)
{
    extern __shared__ __nv_bfloat16 sm[];
    const int t    = threadIdx.x;
    const int wid  = t >> 5;
    const int lane = t & 31;

    const int bh = blockIdx.y;
    const int m0 = blockIdx.x * 128;

    const uint32_t sbase = smem_u32(sm);
    const int warp_m = wid >> 2;
    const int warp_n = wid & 3;

    float acc[4][2][4];
#pragma unroll
    for (int mt = 0; mt < 4; mt++)
#pragma unroll
        for (int nt = 0; nt < 2; nt++)
#pragma unroll
            for (int e = 0; e < 4; e++) acc[mt][nt][e] = 0.f;

    const int l16   = lane & 15;
    const int arow  = warp_m * 64 + (lane & 15);
    const int acol8 = (lane >> 4) * 8;
    const int brow  = warp_n * 16 + (l16 & 7);
    const int bcol8 = (l16 >> 3) * 8;

    const int lrb = t >> 4;          // att: 16 threads/row
    const int c0  = (t & 15) * 4;
    const int vqi = t & 7;           // V: 8 threads/row

    float2 ms[8];
#pragma unroll
    for (int p = 0; p < 8; p++)
        ms[p] = g_rowMS[(size_t)bh * SS + m0 + lrb + p * 16];

    for (int kb = 0; kb < SS; kb += 64) {
        // att chunk: normalize + write back + hi/lo split into smem
#pragma unroll
        for (int p = 0; p < 8; p++) {
            const int row = lrb + p * 16;
            float* ap = att + ((size_t)bh * SS + m0 + row) * SS + kb + c0;
            float4 v = *(const float4*)ap;
            const float M = ms[p].x, inv = ms[p].y;
            v.x = __expf(v.x - M) * inv;
            v.y = __expf(v.y - M) * inv;
            v.z = __expf(v.z - M) * inv;
            v.w = __expf(v.w - M) * inv;
            *(float4*)ap = v;
            __nv_bfloat16 h0,h1,h2,h3,l0,l1,l2,l3;
            split_bf16(v.x,h0,l0); split_bf16(v.y,h1,l1);
            split_bf16(v.z,h2,l2); split_bf16(v.w,h3,l3);
            __nv_bfloat162* ph = (__nv_bfloat162*)(sm + AV_AH + row * SPAD + c0);
            ph[0] = __nv_bfloat162(h0,h1); ph[1] = __nv_bfloat162(h2,h3);
            __nv_bfloat162* pl = (__nv_bfloat162*)(sm + AV_AL + row * SPAD + c0);
            pl[0] = __nv_bfloat162(l0,l1); pl[1] = __nv_bfloat162(l2,l3);
        }
        // V^T chunk: 64 d-rows x 64 s-cols bf16, 8 threads/row, 2 passes
#pragma unroll
        for (int p = 0; p < 2; p++) {
            const int vr = (t >> 3) + p * 32;
            const size_t voff = ((size_t)bh * DH + vr) * SS + kb + vqi * 8;
            *(uint4*)(sm + AV_VH + vr * SPAD + vqi * 8) = *(const uint4*)(g_Vth + voff);
            *(uint4*)(sm + AV_VL + vr * SPAD + vqi * 8) = *(const uint4*)(g_Vtl + voff);
        }
        __syncthreads();

#pragma unroll
        for (int ks = 0; ks < 4; ks++) {
            const int k0 = ks * 16;
            uint32_t aH[4][4], aL[4][4], bH[2][2], bL[2][2];
#pragma unroll
            for (int mt = 0; mt < 4; mt++) {
                ldm_x4(aH[mt], sbase + 2u * (AV_AH + (arow + mt*16) * SPAD + k0 + acol8));
                ldm_x4(aL[mt], sbase + 2u * (AV_AL + (arow + mt*16) * SPAD + k0 + acol8));
            }
#pragma unroll
            for (int nt = 0; nt < 2; nt++) {
                ldm_x2(bH[nt], sbase + 2u * (AV_VH + (brow + nt*8) * SPAD + k0 + bcol8));
                ldm_x2(bL[nt], sbase + 2u * (AV_VL + (brow + nt*8) * SPAD + k0 + bcol8));
            }
#pragma unroll
            for (int mt = 0; mt < 4; mt++)
#pragma unroll
                for (int nt = 0; nt < 2; nt++) {
                    mma16816(acc[mt][nt], aH[mt], bH[nt]);
                    mma16816(acc[mt][nt], aH[mt], bL[nt]);
                    mma16816(acc[mt][nt], aL[mt], bH[nt]);
                }
        }
        __syncthreads();
    }

    // Epilogue -> g_Hh/g_Hl bf16 hi/lo, [bh][s][d]
    const int orow = m0 + warp_m * 64 + (lane >> 2);
    const int ocb0 = warp_n * 16 + (lane & 3) * 2;
#pragma unroll
    for (int mt = 0; mt < 4; mt++) {
#pragma unroll
        for (int rr = 0; rr < 2; rr++) {
            const int r = orow + mt * 16 + rr * 8;
#pragma unroll
            for (int nt = 0; nt < 2; nt++) {
                const int cb = ocb0 + nt * 8;
                const float v0 = acc[mt][nt][rr*2+0];
                const float v1 = acc[mt][nt][rr*2+1];
                __nv_bfloat16 h0,h1,l0,l1;
                split_bf16(v0,h0,l0); split_bf16(v1,h1,l1);
                const size_t idx = ((size_t)bh * SS + r) * DH + cb;
                *(__nv_bfloat162*)(g_Hh + idx) = __nv_bfloat162(h0,h1);
                *(__nv_bfloat162*)(g_Hl + idx) = __nv_bfloat162(l0,l1);
            }
        }
    }
}

// ---------------------------------------------------------------------------
// Kernel 5: output projection via mma.sync: out = H @ Wo^T + bo.
// grid (4, 64), block 256
// ---------------------------------------------------------------------------
__global__ __launch_bounds__(256, 2)
void oproj_mma_kernel(const float* __restrict__ Wo, const float* __restrict__ bo,
                      float* __restrict__ out)
{
    extern __shared__ __nv_bfloat16 sm[];
    const int t    = threadIdx.x;
    const int wid  = t >> 5;
    const int lane = t & 31;
    const int m0   = blockIdx.y * 128;
    const int n0   = blockIdx.x * 128;
    const int b_   = m0 >> 11;
    const int s0   = m0 & 2047;

    const uint32_t sbase = smem_u32(sm);
    const int warp_m = wid >> 2;
    const int warp_n = wid & 3;

    float acc[4][4][4];
#pragma unroll
    for (int mt = 0; mt < 4; mt++)
#pragma unroll
        for (int nt = 0; nt < 4; nt++)
#pragma unroll
            for (int e = 0; e < 4; e++) acc[mt][nt][e] = 0.f;

    const int l16   = lane & 15;
    const int arow  = warp_m * 64 + (lane & 15);
    const int acol8 = (lane >> 4) * 8;
    const int brow  = warp_n * 32 + (l16 & 7);
    const int bcol8 = (l16 >> 3) * 8;

    const int aqi = t & 7;
    const int wlr = t >> 4;
    const int wc0 = (t & 15) * 4;

    for (int kb = 0; kb < 8; kb++) {
#pragma unroll
        for (int p = 0; p < 4; p++) {
            const int row = (t >> 3) + p * 32;
            const size_t hoff = (((size_t)(b_ * Hh + kb) * SS) + s0 + row) * DH + aqi * 8;
            *(uint4*)(sm + T_AH + row * SPAD + aqi * 8) = *(const uint4*)(g_Hh + hoff);
            *(uint4*)(sm + T_AL + row * SPAD + aqi * 8) = *(const uint4*)(g_Hl + hoff);
        }
#pragma unroll
        for (int p = 0; p < 8; p++) {
            const int row = wlr + p * 16;
            float4 wv = *(const float4*)(Wo + (size_t)(n0 + row) * DM + kb * 64 + wc0);
            __nv_bfloat16 h0,h1,h2,h3,l0,l1,l2,l3;
            split_bf16(wv.x,h0,l0); split_bf16(wv.y,h1,l1);
            split_bf16(wv.z,h2,l2); split_bf16(wv.w,h3,l3);
            __nv_bfloat162* pb = (__nv_bfloat162*)(sm + T_BH + row * SPAD + wc0);
            pb[0] = __nv_bfloat162(h0,h1); pb[1] = __nv_bfloat162(h2,h3);
            __nv_bfloat162* qb = (__nv_bfloat162*)(sm + T_BL + row * SPAD + wc0);
            qb[0] = __nv_bfloat162(l0,l1); qb[1] = __nv_bfloat162(l2,l3);
        }
        __syncthreads();

#pragma unroll
        for (int c = 0; c < 3; c++) {
            const int Aoff = (c < 2) ? T_AH : T_AL;
            const int Boff = (c == 1) ? T_BL : T_BH;
#pragma unroll
            for (int ks = 0; ks < 4; ks++) {
                const int k0 = ks * 16;
                uint32_t a[4][4], b[4][2];
#pragma unroll
                for (int mt = 0; mt < 4; mt++)
                    ldm_x4(a[mt], sbase + 2u * (Aoff + (arow + mt*16) * SPAD + k0 + acol8));
#pragma unroll
                for (int nt = 0; nt < 4; nt++)
                    ldm_x2(b[nt], sbase + 2u * (Boff + (brow + nt*8) * SPAD + k0 + bcol8));
#pragma unroll
                for (int mt = 0; mt < 4; mt++)
#pragma unroll
                    for (int nt = 0; nt < 4; nt++)
                        mma16816(acc[mt][nt], a[mt], b[nt]);
            }
        }
        __syncthreads();
    }

    const int lr0 = warp_m * 64 + (lane >> 2);
    const int cb0 = warp_n * 32 + (lane & 3) * 2;
#pragma unroll
    for (int mt = 0; mt < 4; mt++) {
#pragma unroll
        for (int rr = 0; rr < 2; rr++) {
            const int mm = m0 + lr0 + mt * 16 + rr * 8;
#pragma unroll
            for (int nt = 0; nt < 4; nt++) {
                const int n = n0 + cb0 + nt * 8;
                *(float2*)(out + (size_t)mm * DM + n) =
                    make_float2(acc[mt][nt][rr*2+0] + bo[n],
                                acc[mt][nt][rr*2+1] + bo[n+1]);
            }
        }
    }
}

// ---------------------------------------------------------------------------
extern "C" void kernel_launch(void* const* d_in, const int* in_sizes, int n_in,
                              void* d_out, int out_size)
{
    const float* queries = (const float*)d_in[0];
    const float* keys    = (const float*)d_in[1];
    const float* values  = (const float*)d_in[2];
    const float* mask    = (const float*)d_in[3];
    const float* Wq      = (const float*)d_in[4];
    const float* bq      = (const float*)d_in[5];
    const float* Wk      = (const float*)d_in[6];
    const float* bk      = (const float*)d_in[7];
    const float* Wv      = (const float*)d_in[8];
    const float* bv      = (const float*)d_in[9];
    const float* Wo      = (const float*)d_in[10];
    const float* bo      = (const float*)d_in[11];

    float* out = (float*)d_out;            // [4, 2048, 512]
    float* att = out + OUT_ELEMS;          // [4, 8, 2048, 2048]

    cudaFuncSetAttribute(proj_mma_kernel,
                         cudaFuncAttributeMaxDynamicSharedMemorySize, OPER_SMEM);
    cudaFuncSetAttribute(scores_mma_kernel,
                         cudaFuncAttributeMaxDynamicSharedMemorySize, OPER_SMEM);
    cudaFuncSetAttribute(av_mma_kernel,
                         cudaFuncAttributeMaxDynamicSharedMemorySize, AV_SMEM);
    cudaFuncSetAttribute(oproj_mma_kernel,
                         cudaFuncAttributeMaxDynamicSharedMemorySize, OPER_SMEM);

    dim3 projGrid(DM / 128, MQ / 128, 3);  // (4, 64, 3)
    proj_mma_kernel<<<projGrid, 256, OPER_SMEM>>>(queries, keys, values,
                                                  Wq, Wk, Wv, bq, bk, bv);

    dim3 scoreGrid(SS / 128, SS / 128, BHN);  // (16, 16, 32)
    scores_mma_kernel<<<scoreGrid, 256, OPER_SMEM>>>(mask, att);

    reduce_stats_kernel<<<(BHN * SS) / 256, 256>>>();

    dim3 avGrid(SS / 128, BHN);            // (16, 32)
    av_mma_kernel<<<avGrid, 256, AV_SMEM>>>(att);

    dim3 oGrid(DM / 128, MQ / 128);        // (4, 64)
    oproj_mma_kernel<<<oGrid, 256, OPER_SMEM>>>(Wo, bo, out);
}